// round 1
// baseline (speedup 1.0000x reference)
#include <cuda_runtime.h>
#include <cstdint>

#define N_NODES 50000
#define N_EDGES 600000
#define D 128
#define TILE 128
#define NTHREADS 256
#define LN_EPS 1e-5f

// Scratch aggregation buffer (device global: no allocations allowed)
__device__ float g_agg[N_NODES * D];

// ---------------- packed f32x2 helpers (FFMA2: full-rate fp32 on sm_103a) ---
__device__ __forceinline__ unsigned long long pack2(float lo, float hi) {
    unsigned long long r;
    asm("mov.b64 %0, {%1, %2};" : "=l"(r) : "f"(lo), "f"(hi));
    return r;
}
__device__ __forceinline__ void unpack2(unsigned long long v, float& lo, float& hi) {
    asm("mov.b64 {%0, %1}, %2;" : "=f"(lo), "=f"(hi) : "l"(v));
}
__device__ __forceinline__ void ffma2(unsigned long long& d, unsigned long long a,
                                      unsigned long long b) {
    asm("fma.rn.f32x2 %0, %1, %2, %0;" : "+l"(d) : "l"(a), "l"(b));
}

// 128x128x128 GEMM tile core: X[128][128] (smem) x W[128][128] (smem) += acc.
// Thread (tx,ty) of 16x16 owns rows r0..r0+7, cols c0..c0+7 (as 4 f32x2 pairs).
__device__ __forceinline__ void gemm_tile(const float* __restrict__ Xs,
                                          const float* __restrict__ Ws,
                                          int r0, int c0,
                                          unsigned long long (&acc)[8][4]) {
#pragma unroll 2
    for (int k = 0; k < 128; k += 4) {
        float4 a4[8];
#pragma unroll
        for (int i = 0; i < 8; ++i)
            a4[i] = *(const float4*)&Xs[(r0 + i) * 128 + k];
#pragma unroll
        for (int kk = 0; kk < 4; ++kk) {
            unsigned long long bb[4];
            const unsigned long long* wrow =
                (const unsigned long long*)(Ws + (k + kk) * 128 + c0);
#pragma unroll
            for (int j = 0; j < 4; ++j) bb[j] = wrow[j];
#pragma unroll
            for (int i = 0; i < 8; ++i) {
                float av = (kk == 0) ? a4[i].x : (kk == 1) ? a4[i].y
                          : (kk == 2) ? a4[i].z : a4[i].w;
                unsigned long long aa = pack2(av, av);
#pragma unroll
                for (int j = 0; j < 4; ++j) ffma2(acc[i][j], aa, bb[j]);
            }
        }
    }
}

// ---------------------------------------------------------------------------
__global__ void zero_agg_kernel() {
    int i = blockIdx.x * blockDim.x + threadIdx.x;  // exactly N*D/4 threads
    ((float4*)g_agg)[i] = make_float4(0.f, 0.f, 0.f, 0.f);
}

// ---------------------------------------------------------------------------
// Edge kernel: per block, 128 edges.
// x = [node[s] | node[r] | edge]  (3 K-chunks of 128)
// h = relu(x @ We1 + be1); y = h @ We2 + be2; m = LN(y)*ge+bbe
// out_edge = m + edge_feat ; atomicAdd(agg[receiver], m)
__global__ void __launch_bounds__(NTHREADS)
edge_kernel(const float* __restrict__ nf, const float* __restrict__ ef,
            const int* __restrict__ snd, const int* __restrict__ rcv,
            const float* __restrict__ We1, const float* __restrict__ be1,
            const float* __restrict__ We2, const float* __restrict__ be2,
            const float* __restrict__ ge, const float* __restrict__ bbe,
            float* __restrict__ out_edges) {
    extern __shared__ float smem[];
    float* Xs = smem;               // 128*128
    float* Ws = smem + 16384;       // 128*128
    float* Es = smem + 32768;       // 128*128 (edge features, kept for residual)

    const int tid = threadIdx.x;
    const int ebase = blockIdx.x * TILE;
    const int valid = min(TILE, N_EDGES - ebase);

    const int tx = tid & 15, ty = tid >> 4;
    const int r0 = ty * 8, c0 = tx * 8;

    unsigned long long acc[8][4];
#pragma unroll
    for (int i = 0; i < 8; ++i)
#pragma unroll
        for (int j = 0; j < 4; ++j) acc[i][j] = 0ULL;

    // ---- GEMM1 over 3 K-chunks ----
    for (int chunk = 0; chunk < 3; ++chunk) {
        __syncthreads();
        float* Xdst = (chunk == 2) ? Es : Xs;
        const int* idx = (chunk == 0) ? snd : rcv;
#pragma unroll
        for (int t = 0; t < 16; ++t) {
            int lin = t * NTHREADS + tid;          // 4096 float4
            int row = lin >> 5;
            int c4 = lin & 31;
            if (row < valid) {
                const float* src = (chunk == 2)
                    ? (ef + (size_t)(ebase + row) * D)
                    : (nf + (size_t)idx[ebase + row] * D);
                ((float4*)Xdst)[row * 32 + c4] = ((const float4*)src)[c4];
            }
        }
        const float4* wsrc = (const float4*)(We1 + chunk * 16384);
#pragma unroll
        for (int t = 0; t < 16; ++t) {
            int lin = t * NTHREADS + tid;
            ((float4*)Ws)[lin] = wsrc[lin];
        }
        __syncthreads();
        gemm_tile(Xdst, Ws, r0, c0, acc);
    }

    // ---- ReLU + bias -> Hs (reuse Xs) ----
    __syncthreads();
#pragma unroll
    for (int i = 0; i < 8; ++i)
#pragma unroll
        for (int j = 0; j < 4; ++j) {
            float lo, hi;
            unpack2(acc[i][j], lo, hi);
            int c = c0 + 2 * j;
            float2 hv;
            hv.x = fmaxf(lo + be1[c], 0.f);
            hv.y = fmaxf(hi + be1[c + 1], 0.f);
            *(float2*)&Xs[(r0 + i) * 128 + c] = hv;
            acc[i][j] = 0ULL;
        }
    {
        const float4* wsrc = (const float4*)We2;
#pragma unroll
        for (int t = 0; t < 16; ++t) {
            int lin = t * NTHREADS + tid;
            ((float4*)Ws)[lin] = wsrc[lin];
        }
    }
    __syncthreads();
    gemm_tile(Xs, Ws, r0, c0, acc);

    // ---- y = acc + be2 -> smem (reuse Xs) ----
    __syncthreads();
#pragma unroll
    for (int i = 0; i < 8; ++i)
#pragma unroll
        for (int j = 0; j < 4; ++j) {
            float lo, hi;
            unpack2(acc[i][j], lo, hi);
            int c = c0 + 2 * j;
            float2 yv;
            yv.x = lo + be2[c];
            yv.y = hi + be2[c + 1];
            *(float2*)&Xs[(r0 + i) * 128 + c] = yv;
        }
    __syncthreads();

    // ---- LayerNorm + residual + scatter (warp per row) ----
    const int wid = tid >> 5, lane = tid & 31;
    const float4 g4 = ((const float4*)ge)[lane];
    const float4 b4 = ((const float4*)bbe)[lane];
    for (int r = wid; r < valid; r += 8) {
        float4 v = ((float4*)(Xs + r * 128))[lane];
        float s = v.x + v.y + v.z + v.w;
        float ss = v.x * v.x + v.y * v.y + v.z * v.z + v.w * v.w;
#pragma unroll
        for (int off = 16; off; off >>= 1) {
            s += __shfl_xor_sync(0xffffffffu, s, off);
            ss += __shfl_xor_sync(0xffffffffu, ss, off);
        }
        float mu = s * (1.f / 128.f);
        float var = ss * (1.f / 128.f) - mu * mu;
        float inv = rsqrtf(var + LN_EPS);
        int e = ebase + r;
        int rv = rcv[e];
        float m0 = (v.x - mu) * inv * g4.x + b4.x;
        float m1 = (v.y - mu) * inv * g4.y + b4.y;
        float m2 = (v.z - mu) * inv * g4.z + b4.z;
        float m3 = (v.w - mu) * inv * g4.w + b4.w;
        float* ap = g_agg + (size_t)rv * D + lane * 4;
        atomicAdd(ap + 0, m0);
        atomicAdd(ap + 1, m1);
        atomicAdd(ap + 2, m2);
        atomicAdd(ap + 3, m3);
        float4 res = ((float4*)(Es + r * 128))[lane];
        float4 o;
        o.x = m0 + res.x; o.y = m1 + res.y; o.z = m2 + res.z; o.w = m3 + res.w;
        ((float4*)(out_edges + (size_t)e * D))[lane] = o;
    }
}

// ---------------------------------------------------------------------------
// Node kernel: per block, 128 nodes.
// x = [node | agg] (2 K-chunks); MLP; LN*gn+bbn; + node residual.
__global__ void __launch_bounds__(NTHREADS)
node_kernel(const float* __restrict__ nf,
            const float* __restrict__ Wn1, const float* __restrict__ bn1,
            const float* __restrict__ Wn2, const float* __restrict__ bn2,
            const float* __restrict__ gn, const float* __restrict__ bbn,
            float* __restrict__ out_nodes) {
    extern __shared__ float smem[];
    float* Xs = smem;               // chunk-1 input, then H, then Y
    float* Ws = smem + 16384;
    float* Ns = smem + 32768;       // node features (chunk 0 + residual)

    const int tid = threadIdx.x;
    const int nbase = blockIdx.x * TILE;
    const int valid = min(TILE, N_NODES - nbase);

    const int tx = tid & 15, ty = tid >> 4;
    const int r0 = ty * 8, c0 = tx * 8;

    unsigned long long acc[8][4];
#pragma unroll
    for (int i = 0; i < 8; ++i)
#pragma unroll
        for (int j = 0; j < 4; ++j) acc[i][j] = 0ULL;

    for (int chunk = 0; chunk < 2; ++chunk) {
        __syncthreads();
        float* Xdst = (chunk == 0) ? Ns : Xs;
        const float* srcbase = (chunk == 0) ? nf : g_agg;
#pragma unroll
        for (int t = 0; t < 16; ++t) {
            int lin = t * NTHREADS + tid;
            int row = lin >> 5;
            int c4 = lin & 31;
            if (row < valid) {
                const float* src = srcbase + (size_t)(nbase + row) * D;
                ((float4*)Xdst)[row * 32 + c4] = ((const float4*)src)[c4];
            }
        }
        const float4* wsrc = (const float4*)(Wn1 + chunk * 16384);
#pragma unroll
        for (int t = 0; t < 16; ++t) {
            int lin = t * NTHREADS + tid;
            ((float4*)Ws)[lin] = wsrc[lin];
        }
        __syncthreads();
        gemm_tile(Xdst, Ws, r0, c0, acc);
    }

    __syncthreads();
#pragma unroll
    for (int i = 0; i < 8; ++i)
#pragma unroll
        for (int j = 0; j < 4; ++j) {
            float lo, hi;
            unpack2(acc[i][j], lo, hi);
            int c = c0 + 2 * j;
            float2 hv;
            hv.x = fmaxf(lo + bn1[c], 0.f);
            hv.y = fmaxf(hi + bn1[c + 1], 0.f);
            *(float2*)&Xs[(r0 + i) * 128 + c] = hv;
            acc[i][j] = 0ULL;
        }
    {
        const float4* wsrc = (const float4*)Wn2;
#pragma unroll
        for (int t = 0; t < 16; ++t) {
            int lin = t * NTHREADS + tid;
            ((float4*)Ws)[lin] = wsrc[lin];
        }
    }
    __syncthreads();
    gemm_tile(Xs, Ws, r0, c0, acc);

    __syncthreads();
#pragma unroll
    for (int i = 0; i < 8; ++i)
#pragma unroll
        for (int j = 0; j < 4; ++j) {
            float lo, hi;
            unpack2(acc[i][j], lo, hi);
            int c = c0 + 2 * j;
            float2 yv;
            yv.x = lo + bn2[c];
            yv.y = hi + bn2[c + 1];
            *(float2*)&Xs[(r0 + i) * 128 + c] = yv;
        }
    __syncthreads();

    const int wid = tid >> 5, lane = tid & 31;
    const float4 g4 = ((const float4*)gn)[lane];
    const float4 b4 = ((const float4*)bbn)[lane];
    for (int r = wid; r < valid; r += 8) {
        float4 v = ((float4*)(Xs + r * 128))[lane];
        float s = v.x + v.y + v.z + v.w;
        float ss = v.x * v.x + v.y * v.y + v.z * v.z + v.w * v.w;
#pragma unroll
        for (int off = 16; off; off >>= 1) {
            s += __shfl_xor_sync(0xffffffffu, s, off);
            ss += __shfl_xor_sync(0xffffffffu, ss, off);
        }
        float mu = s * (1.f / 128.f);
        float var = ss * (1.f / 128.f) - mu * mu;
        float inv = rsqrtf(var + LN_EPS);
        float4 res = ((float4*)(Ns + r * 128))[lane];
        float4 o;
        o.x = (v.x - mu) * inv * g4.x + b4.x + res.x;
        o.y = (v.y - mu) * inv * g4.y + b4.y + res.y;
        o.z = (v.z - mu) * inv * g4.z + b4.z + res.z;
        o.w = (v.w - mu) * inv * g4.w + b4.w + res.w;
        ((float4*)(out_nodes + (size_t)(nbase + r) * D))[lane] = o;
    }
}

// ---------------------------------------------------------------------------
extern "C" void kernel_launch(void* const* d_in, const int* in_sizes, int n_in,
                              void* d_out, int out_size) {
    const float* nf  = (const float*)d_in[0];
    const float* ef  = (const float*)d_in[1];
    const int*   snd = (const int*)d_in[2];
    const int*   rcv = (const int*)d_in[3];
    const float* We1 = (const float*)d_in[4];
    const float* be1 = (const float*)d_in[5];
    const float* We2 = (const float*)d_in[6];
    const float* be2 = (const float*)d_in[7];
    const float* ge  = (const float*)d_in[8];
    const float* bbe = (const float*)d_in[9];
    const float* Wn1 = (const float*)d_in[10];
    const float* bn1 = (const float*)d_in[11];
    const float* Wn2 = (const float*)d_in[12];
    const float* bn2 = (const float*)d_in[13];
    const float* gn  = (const float*)d_in[14];
    const float* bbn = (const float*)d_in[15];

    float* out_nodes = (float*)d_out;
    float* out_edges = out_nodes + (size_t)N_NODES * D;

    const int smem_bytes = 3 * 128 * 128 * (int)sizeof(float);  // 196608
    cudaFuncSetAttribute(edge_kernel, cudaFuncAttributeMaxDynamicSharedMemorySize,
                         smem_bytes);
    cudaFuncSetAttribute(node_kernel, cudaFuncAttributeMaxDynamicSharedMemorySize,
                         smem_bytes);

    zero_agg_kernel<<<(N_NODES * D / 4) / NTHREADS, NTHREADS>>>();

    int eblocks = (N_EDGES + TILE - 1) / TILE;  // 4688
    edge_kernel<<<eblocks, NTHREADS, smem_bytes>>>(
        nf, ef, snd, rcv, We1, be1, We2, be2, ge, bbe, out_edges);

    int nblocks = (N_NODES + TILE - 1) / TILE;  // 391
    node_kernel<<<nblocks, NTHREADS, smem_bytes>>>(
        nf, Wn1, bn1, Wn2, bn2, gn, bbn, out_nodes);
}

// round 3
// speedup vs baseline: 1.8395x; 1.8395x over previous
#include <cuda_runtime.h>
#include <cuda_bf16.h>
#include <cstdint>

#define N_NODES 50000
#define N_EDGES 600000
#define LN_EPS 1e-5f

#define LDA 136                         // halves per row (16B pad: conflict-free ldmatrix)
#define TILE_HALVES (128 * LDA)         // 17408
#define TILE_BYTES  (TILE_HALVES * 2)   // 34816
#define CHUNK_HALVES (2 * TILE_HALVES)  // hi + lo
#define CHUNK_BYTES  (2 * TILE_BYTES)   // 69632

// ---------------- device-global scratch (no allocations allowed) ------------
__device__ float g_agg[N_NODES * 128];
// Pre-split, pre-transposed weights as B[n][k] (row-major over k), padded LDA.
// Edge: chunks 0-2 = We1 (K=384), 3 = We2. Node: 0-1 = Wn1 (K=256), 2 = Wn2.
__device__ __nv_bfloat16 g_We[4 * CHUNK_HALVES];
__device__ __nv_bfloat16 g_Wn[3 * CHUNK_HALVES];

// ---------------- smem layout (bytes) ---------------------------------------
#define XA_OFF    0                     // X/H tile: hi then lo (69632)
#define WB_OFF    CHUNK_BYTES           // W tile: hi then lo (69632)
#define BIAS1_OFF (2 * CHUNK_BYTES)     // 139264
#define BIAS2_OFF (BIAS1_OFF + 512)
#define GAM_OFF   (BIAS1_OFF + 1024)
#define BET_OFF   (BIAS1_OFF + 1536)
#define SIDX_OFF  (BIAS1_OFF + 2048)
#define RIDX_OFF  (BIAS1_OFF + 2560)
#define PART_OFF  (BIAS1_OFF + 3072)    // float2[128][2]
#define SMEM_TOTAL (PART_OFF + 2048)    // 144384

// ---------------- helpers ----------------------------------------------------
__device__ __forceinline__ uint32_t smem_u32(const void* p) {
    uint32_t a;
    asm("{ .reg .u64 t; cvta.to.shared.u64 t, %1; cvt.u32.u64 %0, t; }"
        : "=r"(a) : "l"(p));
    return a;
}
__device__ __forceinline__ void ldsm4(uint32_t (&r)[4], uint32_t a) {
    asm volatile("ldmatrix.sync.aligned.m8n8.x4.shared.b16 {%0,%1,%2,%3}, [%4];"
                 : "=r"(r[0]), "=r"(r[1]), "=r"(r[2]), "=r"(r[3]) : "r"(a));
}
__device__ __forceinline__ void mma16816(float (&d)[4], const uint32_t (&a)[4],
                                         uint32_t b0, uint32_t b1) {
    asm volatile(
        "mma.sync.aligned.m16n8k16.row.col.f32.bf16.bf16.f32 "
        "{%0,%1,%2,%3}, {%4,%5,%6,%7}, {%8,%9}, {%0,%1,%2,%3};"
        : "+f"(d[0]), "+f"(d[1]), "+f"(d[2]), "+f"(d[3])
        : "r"(a[0]), "r"(a[1]), "r"(a[2]), "r"(a[3]), "r"(b0), "r"(b1));
}
// split fp32 pair -> packed bf16x2 hi (ret) and lo (out param)
__device__ __forceinline__ uint32_t split2(float a, float b, uint32_t& lo) {
    __nv_bfloat16 ha = __float2bfloat16(a), hb = __float2bfloat16(b);
    __nv_bfloat16 la = __float2bfloat16(a - __bfloat162float(ha));
    __nv_bfloat16 lb = __float2bfloat16(b - __bfloat162float(hb));
    lo = ((uint32_t)__bfloat16_as_ushort(lb) << 16) | __bfloat16_as_ushort(la);
    return ((uint32_t)__bfloat16_as_ushort(hb) << 16) | __bfloat16_as_ushort(ha);
}

// One 128x128x128 chunk: acc += (Xhi+Xlo)(Whi+Wlo) via 3-pass bf16.
// aB/bB: this thread's ldmatrix base addresses (k0 = 0) for hi tiles.
__device__ __forceinline__ void compute_chunk(float (&acc)[2][8][4],
                                              uint32_t aB, uint32_t bB) {
#pragma unroll
    for (int ks = 0; ks < 8; ++ks) {
        const uint32_t ko = ks * 32;  // 16 halves * 2 bytes
        uint32_t ah[2][4], al[2][4];
        ldsm4(ah[0], aB + ko);
        ldsm4(ah[1], aB + 16 * LDA * 2 + ko);
        ldsm4(al[0], aB + TILE_BYTES + ko);
        ldsm4(al[1], aB + TILE_BYTES + 16 * LDA * 2 + ko);
#pragma unroll
        for (int nj = 0; nj < 4; ++nj) {
            uint32_t bh[4], bl[4];
            ldsm4(bh, bB + nj * 16 * LDA * 2 + ko);
            ldsm4(bl, bB + TILE_BYTES + nj * 16 * LDA * 2 + ko);
#pragma unroll
            for (int mi = 0; mi < 2; ++mi) {
                mma16816(acc[mi][2 * nj],     ah[mi], bh[0], bh[1]);
                mma16816(acc[mi][2 * nj + 1], ah[mi], bh[2], bh[3]);
                mma16816(acc[mi][2 * nj],     al[mi], bh[0], bh[1]);
                mma16816(acc[mi][2 * nj + 1], al[mi], bh[2], bh[3]);
                mma16816(acc[mi][2 * nj],     ah[mi], bl[0], bl[1]);
                mma16816(acc[mi][2 * nj + 1], ah[mi], bl[2], bl[3]);
            }
        }
    }
}

// ---------------- utility kernels -------------------------------------------
__global__ void zero_agg_kernel() {
    int i = blockIdx.x * blockDim.x + threadIdx.x;
    ((float4*)g_agg)[i] = make_float4(0.f, 0.f, 0.f, 0.f);
}

// Split + transpose weights into g_We / g_Wn as B[n][k] hi/lo, LDA-padded.
__global__ void prep_kernel(const float* __restrict__ We1, const float* __restrict__ We2,
                            const float* __restrict__ Wn1, const float* __restrict__ Wn2) {
    int idx = blockIdx.x * blockDim.x + threadIdx.x;
    if (idx >= 7 * 16384) return;
    int g = idx >> 14;   // chunk 0..6
    int i = idx & 16383;
    int n = i >> 7;      // 0..127
    int k = i & 127;
    float v;
    __nv_bfloat16* basep;
    if (g < 4) {
        basep = g_We + g * CHUNK_HALVES;
        v = (g < 3) ? We1[(g * 128 + k) * 128 + n] : We2[k * 128 + n];
    } else {
        int gn = g - 4;
        basep = g_Wn + gn * CHUNK_HALVES;
        v = (gn < 2) ? Wn1[(gn * 128 + k) * 128 + n] : Wn2[k * 128 + n];
    }
    __nv_bfloat16 hi = __float2bfloat16(v);
    __nv_bfloat16 lo = __float2bfloat16(v - __bfloat162float(hi));
    basep[n * LDA + k] = hi;
    basep[TILE_HALVES + n * LDA + k] = lo;
}

// ---------------- main fused tile kernel -------------------------------------
// EDGE: X = [nf[snd] | nf[rcv] | ef] (NCH=3 chunks of K=128); scatter to g_agg.
// NODE: X = [nf | g_agg] (NCH=2).
template <int NCH, bool EDGE>
__global__ void __launch_bounds__(256, 1)
gnb_kernel(const float* __restrict__ nf, const float* __restrict__ ef,
           const int* __restrict__ snd, const int* __restrict__ rcv,
           const float* __restrict__ b1, const float* __restrict__ b2,
           const float* __restrict__ gam, const float* __restrict__ bet,
           float* __restrict__ out) {
    extern __shared__ char smem[];
    const uint32_t sb = smem_u32(smem);
    const int tid = threadIdx.x, lane = tid & 31, wid = tid >> 5;
    const int wrow = wid >> 1, wcol = wid & 1;
    const int base = blockIdx.x * 128;
    const int valid = min(128, (EDGE ? N_EDGES : N_NODES) - base);
    const __nv_bfloat16* gW = EDGE ? g_We : g_Wn;

    if (tid < 128) {
        ((float*)(smem + BIAS1_OFF))[tid] = b1[tid];
        ((float*)(smem + BIAS2_OFF))[tid] = b2[tid];
        ((float*)(smem + GAM_OFF))[tid] = gam[tid];
        ((float*)(smem + BET_OFF))[tid] = bet[tid];
        if (EDGE) {
            ((int*)(smem + SIDX_OFF))[tid] = (tid < valid) ? snd[base + tid] : 0;
            ((int*)(smem + RIDX_OFF))[tid] = (tid < valid) ? rcv[base + tid] : 0;
        }
    }
    __syncthreads();

    // ldmatrix lane addressing
    const int a_r = lane & 15;                    // A row within 16
    const int a_kb = (lane >> 4) << 3;            // 0 / 8 halves
    const int b_n = (lane & 7) + ((lane >> 4) << 3);
    const int b_kb = ((lane >> 3) & 1) << 3;
    const uint32_t aB = sb + XA_OFF + (uint32_t)((wrow * 32 + a_r) * LDA + a_kb) * 2;
    const uint32_t bB = sb + WB_OFF + (uint32_t)((wcol * 64 + b_n) * LDA + b_kb) * 2;

    const int g = lane >> 2, t4 = lane & 3;

    float acc[2][8][4];
#pragma unroll
    for (int mi = 0; mi < 2; ++mi)
#pragma unroll
        for (int ni = 0; ni < 8; ++ni)
#pragma unroll
            for (int r = 0; r < 4; ++r) acc[mi][ni][r] = 0.f;

    // ---------------- GEMM1 over NCH chunks ---------------------------------
    for (int c = 0; c < NCH; ++c) {
        {   // W chunk copy (69632 B)
            const float4* src = (const float4*)(gW + c * CHUNK_HALVES);
            float4* dst = (float4*)(smem + WB_OFF);
#pragma unroll
            for (int t = 0; t < 17; ++t) dst[t * 256 + tid] = src[t * 256 + tid];
        }
        {   // X gather + split (2 threads per row, 64 cols each)
            const int row = tid >> 1, h = tid & 1;
            const bool ok = row < valid;
            const float* src;
            if (EDGE) {
                if (c == 0)      src = nf + (size_t)((int*)(smem + SIDX_OFF))[row] * 128;
                else if (c == 1) src = nf + (size_t)((int*)(smem + RIDX_OFF))[row] * 128;
                else             src = ef + (size_t)(base + row) * 128;
            } else {
                src = (c ? g_agg : nf) + (size_t)(base + row) * 128;
            }
            src += h * 64;
            char* hi_t = smem + XA_OFF;
            char* lo_t = hi_t + TILE_BYTES;
            const uint32_t ro = (uint32_t)(row * LDA + h * 64) * 2;
#pragma unroll
            for (int j = 0; j < 16; ++j) {
                float4 v = ok ? ((const float4*)src)[j] : make_float4(0.f, 0.f, 0.f, 0.f);
                uint32_t l0, l1;
                uint32_t h0 = split2(v.x, v.y, l0);
                uint32_t h1 = split2(v.z, v.w, l1);
                *(uint32_t*)(hi_t + ro + j * 8) = h0;
                *(uint32_t*)(hi_t + ro + j * 8 + 4) = h1;
                *(uint32_t*)(lo_t + ro + j * 8) = l0;
                *(uint32_t*)(lo_t + ro + j * 8 + 4) = l1;
            }
        }
        __syncthreads();
        compute_chunk(acc, aB, bB);
        __syncthreads();
    }

    // ---------------- epilogue 1: h = relu(y1+b1) -> H tiles; load W2 --------
    {
        const float* s_b1 = (const float*)(smem + BIAS1_OFF);
        char* hi_t = smem + XA_OFF;
        char* lo_t = hi_t + TILE_BYTES;
#pragma unroll
        for (int mi = 0; mi < 2; ++mi) {
            const int r0 = wrow * 32 + mi * 16 + g, r1 = r0 + 8;
#pragma unroll
            for (int ni = 0; ni < 8; ++ni) {
                const int col = wcol * 64 + ni * 8 + t4 * 2;
                const float ba = s_b1[col], bb = s_b1[col + 1];
                float v0 = fmaxf(acc[mi][ni][0] + ba, 0.f);
                float v1 = fmaxf(acc[mi][ni][1] + bb, 0.f);
                float v2 = fmaxf(acc[mi][ni][2] + ba, 0.f);
                float v3 = fmaxf(acc[mi][ni][3] + bb, 0.f);
                uint32_t lo0, lo1;
                uint32_t h0 = split2(v0, v1, lo0);
                uint32_t h1 = split2(v2, v3, lo1);
                const uint32_t o0 = (uint32_t)(r0 * LDA + col) * 2;
                const uint32_t o1 = (uint32_t)(r1 * LDA + col) * 2;
                *(uint32_t*)(hi_t + o0) = h0;
                *(uint32_t*)(lo_t + o0) = lo0;
                *(uint32_t*)(hi_t + o1) = h1;
                *(uint32_t*)(lo_t + o1) = lo1;
            }
        }
        const float4* src = (const float4*)(gW + NCH * CHUNK_HALVES);
        float4* dst = (float4*)(smem + WB_OFF);
#pragma unroll
        for (int t = 0; t < 17; ++t) dst[t * 256 + tid] = src[t * 256 + tid];
    }
    __syncthreads();

    // ---------------- GEMM2 --------------------------------------------------
    float acc2[2][8][4];
#pragma unroll
    for (int mi = 0; mi < 2; ++mi)
#pragma unroll
        for (int ni = 0; ni < 8; ++ni)
#pragma unroll
            for (int r = 0; r < 4; ++r) acc2[mi][ni][r] = 0.f;
    compute_chunk(acc2, aB, bB);

    // ---------------- epilogue 2: LayerNorm + residual + scatter ------------
    {
        const float* s_b2 = (const float*)(smem + BIAS2_OFF);
        float s[2][2] = {{0.f, 0.f}, {0.f, 0.f}};
        float ss[2][2] = {{0.f, 0.f}, {0.f, 0.f}};
#pragma unroll
        for (int mi = 0; mi < 2; ++mi)
#pragma unroll
            for (int ni = 0; ni < 8; ++ni) {
                const int col = wcol * 64 + ni * 8 + t4 * 2;
                const float ba = s_b2[col], bb = s_b2[col + 1];
                float y0 = acc2[mi][ni][0] + ba, y1 = acc2[mi][ni][1] + bb;
                float y2 = acc2[mi][ni][2] + ba, y3 = acc2[mi][ni][3] + bb;
                acc2[mi][ni][0] = y0; acc2[mi][ni][1] = y1;
                acc2[mi][ni][2] = y2; acc2[mi][ni][3] = y3;
                s[mi][0] += y0 + y1; ss[mi][0] += y0 * y0 + y1 * y1;
                s[mi][1] += y2 + y3; ss[mi][1] += y2 * y2 + y3 * y3;
            }
#pragma unroll
        for (int off = 1; off <= 2; off <<= 1)
#pragma unroll
            for (int mi = 0; mi < 2; ++mi)
#pragma unroll
                for (int h = 0; h < 2; ++h) {
                    s[mi][h] += __shfl_xor_sync(0xffffffffu, s[mi][h], off);
                    ss[mi][h] += __shfl_xor_sync(0xffffffffu, ss[mi][h], off);
                }
        float2* part = (float2*)(smem + PART_OFF);
        if (t4 == 0)
#pragma unroll
            for (int mi = 0; mi < 2; ++mi)
#pragma unroll
                for (int h = 0; h < 2; ++h) {
                    const int row = wrow * 32 + mi * 16 + g + h * 8;
                    part[row * 2 + wcol] = make_float2(s[mi][h], ss[mi][h]);
                }
        __syncthreads();

        const float* s_g = (const float*)(smem + GAM_OFF);
        const float* s_bb = (const float*)(smem + BET_OFF);
#pragma unroll
        for (int mi = 0; mi < 2; ++mi)
#pragma unroll
            for (int h = 0; h < 2; ++h) {
                const int row = wrow * 32 + mi * 16 + g + h * 8;
                if (row >= valid) continue;
                float2 p0 = part[row * 2], p1 = part[row * 2 + 1];
                const float mu = (p0.x + p1.x) * (1.f / 128.f);
                const float var = (p0.y + p1.y) * (1.f / 128.f) - mu * mu;
                const float inv = rsqrtf(var + LN_EPS);
                const size_t gro = (size_t)(base + row) * 128;
                const float* res = (EDGE ? ef : nf) + gro;
                float* op = out + gro;
                float* ap = nullptr;
                if (EDGE) {
                    const int rv = ((int*)(smem + RIDX_OFF))[row];
                    ap = g_agg + (size_t)rv * 128;
                }
#pragma unroll
                for (int ni = 0; ni < 8; ++ni) {
                    const int col = wcol * 64 + ni * 8 + t4 * 2;
                    const float y0 = acc2[mi][ni][h * 2];
                    const float y1 = acc2[mi][ni][h * 2 + 1];
                    const float m0 = (y0 - mu) * inv * s_g[col] + s_bb[col];
                    const float m1 = (y1 - mu) * inv * s_g[col + 1] + s_bb[col + 1];
                    if (EDGE) {
                        atomicAdd(ap + col, m0);
                        atomicAdd(ap + col + 1, m1);
                    }
                    float2 r2 = *(const float2*)(res + col);
                    *(float2*)(op + col) = make_float2(m0 + r2.x, m1 + r2.y);
                }
            }
    }
}

// ---------------------------------------------------------------------------
extern "C" void kernel_launch(void* const* d_in, const int* in_sizes, int n_in,
                              void* d_out, int out_size) {
    const float* nf  = (const float*)d_in[0];
    const float* ef  = (const float*)d_in[1];
    const int*   snd = (const int*)d_in[2];
    const int*   rcv = (const int*)d_in[3];
    const float* We1 = (const float*)d_in[4];
    const float* be1 = (const float*)d_in[5];
    const float* We2 = (const float*)d_in[6];
    const float* be2 = (const float*)d_in[7];
    const float* ge  = (const float*)d_in[8];
    const float* bbe = (const float*)d_in[9];
    const float* Wn1 = (const float*)d_in[10];
    const float* bn1 = (const float*)d_in[11];
    const float* Wn2 = (const float*)d_in[12];
    const float* bn2 = (const float*)d_in[13];
    const float* gn  = (const float*)d_in[14];
    const float* bbn = (const float*)d_in[15];

    float* out_nodes = (float*)d_out;
    float* out_edges = out_nodes + (size_t)N_NODES * 128;

    cudaFuncSetAttribute(gnb_kernel<3, true>,
                         cudaFuncAttributeMaxDynamicSharedMemorySize, SMEM_TOTAL);
    cudaFuncSetAttribute(gnb_kernel<2, false>,
                         cudaFuncAttributeMaxDynamicSharedMemorySize, SMEM_TOTAL);

    prep_kernel<<<(7 * 16384 + 255) / 256, 256>>>(We1, We2, Wn1, Wn2);
    zero_agg_kernel<<<(N_NODES * 128 / 4) / 256, 256>>>();

    const int eblocks = (N_EDGES + 127) / 128;  // 4688
    gnb_kernel<3, true><<<eblocks, 256, SMEM_TOTAL>>>(
        nf, ef, snd, rcv, be1, be2, ge, bbe, out_edges);

    const int nblocks = (N_NODES + 127) / 128;  // 391
    gnb_kernel<2, false><<<nblocks, 256, SMEM_TOTAL>>>(
        nf, nullptr, nullptr, nullptr, bn1, bn2, gn, bbn, out_nodes);
}

// round 4
// speedup vs baseline: 1.9371x; 1.0530x over previous
#include <cuda_runtime.h>
#include <cuda_bf16.h>
#include <cstdint>

#define N_NODES 50000
#define N_EDGES 600000
#define LN_EPS 1e-5f

#define LDA 136                         // halves per row (16B pad: conflict-free ldmatrix)
#define TILE_HALVES (128 * LDA)         // 17408
#define TILE_BYTES  (TILE_HALVES * 2)   // 34816
#define CHUNK_HALVES (2 * TILE_HALVES)  // hi + lo
#define CHUNK_BYTES  (2 * TILE_BYTES)   // 69632

// ---------------- device-global scratch (no allocations allowed) ------------
__device__ float g_agg[N_NODES * 128];
// Pre-split, pre-transposed weights as B[n][k] (row-major over k), padded LDA.
// Edge: chunks 0-2 = We1 (K=384), 3 = We2. Node: 0-1 = Wn1 (K=256), 2 = Wn2.
__device__ __nv_bfloat16 g_We[4 * CHUNK_HALVES];
__device__ __nv_bfloat16 g_Wn[3 * CHUNK_HALVES];

// ---------------- smem layout (bytes) ---------------------------------------
#define XA_OFF    0                     // X/H tile: hi then lo (69632)
#define WB_OFF    CHUNK_BYTES           // W tile: hi then lo (69632)
#define BIAS1_OFF (2 * CHUNK_BYTES)     // 139264
#define BIAS2_OFF (BIAS1_OFF + 512)
#define GAM_OFF   (BIAS1_OFF + 1024)
#define BET_OFF   (BIAS1_OFF + 1536)
#define SIDX_OFF  (BIAS1_OFF + 2048)
#define RIDX_OFF  (BIAS1_OFF + 2560)
#define PART_OFF  (BIAS1_OFF + 3072)    // float2[128][4]
#define SMEM_TOTAL (PART_OFF + 4096)    // 146432

// ---------------- helpers ----------------------------------------------------
__device__ __forceinline__ uint32_t smem_u32(const void* p) {
    uint32_t a;
    asm("{ .reg .u64 t; cvta.to.shared.u64 t, %1; cvt.u32.u64 %0, t; }"
        : "=r"(a) : "l"(p));
    return a;
}
__device__ __forceinline__ void ldsm4(uint32_t (&r)[4], uint32_t a) {
    asm volatile("ldmatrix.sync.aligned.m8n8.x4.shared.b16 {%0,%1,%2,%3}, [%4];"
                 : "=r"(r[0]), "=r"(r[1]), "=r"(r[2]), "=r"(r[3]) : "r"(a));
}
__device__ __forceinline__ void mma16816(float (&d)[4], const uint32_t (&a)[4],
                                         uint32_t b0, uint32_t b1) {
    asm volatile(
        "mma.sync.aligned.m16n8k16.row.col.f32.bf16.bf16.f32 "
        "{%0,%1,%2,%3}, {%4,%5,%6,%7}, {%8,%9}, {%0,%1,%2,%3};"
        : "+f"(d[0]), "+f"(d[1]), "+f"(d[2]), "+f"(d[3])
        : "r"(a[0]), "r"(a[1]), "r"(a[2]), "r"(a[3]), "r"(b0), "r"(b1));
}
__device__ __forceinline__ void red_add_v2(float* p, float a, float b) {
    asm volatile("red.global.add.v2.f32 [%0], {%1, %2};"
                 :: "l"(p), "f"(a), "f"(b) : "memory");
}
// split fp32 pair -> packed bf16x2 hi (ret) and lo (out param)
__device__ __forceinline__ uint32_t split2(float a, float b, uint32_t& lo) {
    __nv_bfloat16 ha = __float2bfloat16(a), hb = __float2bfloat16(b);
    __nv_bfloat16 la = __float2bfloat16(a - __bfloat162float(ha));
    __nv_bfloat16 lb = __float2bfloat16(b - __bfloat162float(hb));
    lo = ((uint32_t)__bfloat16_as_ushort(lb) << 16) | __bfloat16_as_ushort(la);
    return ((uint32_t)__bfloat16_as_ushort(hb) << 16) | __bfloat16_as_ushort(ha);
}

// One 128x128x128 chunk, warp tile 32x32: acc += (Xhi+Xlo)(Whi+Wlo), 3-pass bf16.
// Pass-major MMA order: accumulator reuse distance = 8 independent MMAs.
__device__ __forceinline__ void compute_chunk(float (&acc)[2][4][4],
                                              uint32_t aB, uint32_t bB) {
#pragma unroll
    for (int ks = 0; ks < 8; ++ks) {
        const uint32_t ko = ks * 32;  // 16 halves * 2 bytes
        uint32_t ah[2][4], al[2][4], bh[2][4], bl[2][4];
        ldsm4(ah[0], aB + ko);
        ldsm4(ah[1], aB + 16 * LDA * 2 + ko);
        ldsm4(al[0], aB + TILE_BYTES + ko);
        ldsm4(al[1], aB + TILE_BYTES + 16 * LDA * 2 + ko);
        ldsm4(bh[0], bB + ko);
        ldsm4(bh[1], bB + 16 * LDA * 2 + ko);
        ldsm4(bl[0], bB + TILE_BYTES + ko);
        ldsm4(bl[1], bB + TILE_BYTES + 16 * LDA * 2 + ko);
        // pass 1: hi x hi  (8 independent MMAs)
#pragma unroll
        for (int mi = 0; mi < 2; ++mi)
#pragma unroll
            for (int nj = 0; nj < 2; ++nj) {
                mma16816(acc[mi][2 * nj],     ah[mi], bh[nj][0], bh[nj][1]);
                mma16816(acc[mi][2 * nj + 1], ah[mi], bh[nj][2], bh[nj][3]);
            }
        // pass 2: lo x hi
#pragma unroll
        for (int mi = 0; mi < 2; ++mi)
#pragma unroll
            for (int nj = 0; nj < 2; ++nj) {
                mma16816(acc[mi][2 * nj],     al[mi], bh[nj][0], bh[nj][1]);
                mma16816(acc[mi][2 * nj + 1], al[mi], bh[nj][2], bh[nj][3]);
            }
        // pass 3: hi x lo
#pragma unroll
        for (int mi = 0; mi < 2; ++mi)
#pragma unroll
            for (int nj = 0; nj < 2; ++nj) {
                mma16816(acc[mi][2 * nj],     ah[mi], bl[nj][0], bl[nj][1]);
                mma16816(acc[mi][2 * nj + 1], ah[mi], bl[nj][2], bl[nj][3]);
            }
    }
}

// ---------------- utility kernels -------------------------------------------
__global__ void zero_agg_kernel() {
    int i = blockIdx.x * blockDim.x + threadIdx.x;
    ((float4*)g_agg)[i] = make_float4(0.f, 0.f, 0.f, 0.f);
}

// Split + transpose weights into g_We / g_Wn as B[n][k] hi/lo, LDA-padded.
__global__ void prep_kernel(const float* __restrict__ We1, const float* __restrict__ We2,
                            const float* __restrict__ Wn1, const float* __restrict__ Wn2) {
    int idx = blockIdx.x * blockDim.x + threadIdx.x;
    if (idx >= 7 * 16384) return;
    int g = idx >> 14;   // chunk 0..6
    int i = idx & 16383;
    int n = i >> 7;      // 0..127
    int k = i & 127;
    float v;
    __nv_bfloat16* basep;
    if (g < 4) {
        basep = g_We + g * CHUNK_HALVES;
        v = (g < 3) ? We1[(g * 128 + k) * 128 + n] : We2[k * 128 + n];
    } else {
        int gn = g - 4;
        basep = g_Wn + gn * CHUNK_HALVES;
        v = (gn < 2) ? Wn1[(gn * 128 + k) * 128 + n] : Wn2[k * 128 + n];
    }
    __nv_bfloat16 hi = __float2bfloat16(v);
    __nv_bfloat16 lo = __float2bfloat16(v - __bfloat162float(hi));
    basep[n * LDA + k] = hi;
    basep[TILE_HALVES + n * LDA + k] = lo;
}

// ---------------- main fused tile kernel -------------------------------------
// 512 threads, 4x4 warp grid, warp tile 32x32.
// EDGE: X = [nf[snd] | nf[rcv] | ef] (NCH=3 chunks of K=128); scatter to g_agg.
// NODE: X = [nf | g_agg] (NCH=2).
template <int NCH, bool EDGE>
__global__ void __launch_bounds__(512, 1)
gnb_kernel(const float* __restrict__ nf, const float* __restrict__ ef,
           const int* __restrict__ snd, const int* __restrict__ rcv,
           const float* __restrict__ b1, const float* __restrict__ b2,
           const float* __restrict__ gam, const float* __restrict__ bet,
           float* __restrict__ out) {
    extern __shared__ char smem[];
    const uint32_t sb = smem_u32(smem);
    const int tid = threadIdx.x, lane = tid & 31, wid = tid >> 5;
    const int wrow = wid >> 2, wcol = wid & 3;
    const int base = blockIdx.x * 128;
    const int valid = min(128, (EDGE ? N_EDGES : N_NODES) - base);
    const __nv_bfloat16* gW = EDGE ? g_We : g_Wn;

    if (tid < 128) {
        ((float*)(smem + BIAS1_OFF))[tid] = b1[tid];
        ((float*)(smem + BIAS2_OFF))[tid] = b2[tid];
        ((float*)(smem + GAM_OFF))[tid] = gam[tid];
        ((float*)(smem + BET_OFF))[tid] = bet[tid];
        if (EDGE) {
            ((int*)(smem + SIDX_OFF))[tid] = (tid < valid) ? snd[base + tid] : 0;
            ((int*)(smem + RIDX_OFF))[tid] = (tid < valid) ? rcv[base + tid] : 0;
        }
    }
    __syncthreads();

    // ldmatrix lane addressing
    const int a_r = lane & 15;                    // A row within 16
    const int a_kb = (lane >> 4) << 3;            // 0 / 8 halves
    const int b_n = (lane & 7) + ((lane >> 4) << 3);
    const int b_kb = ((lane >> 3) & 1) << 3;
    const uint32_t aB = sb + XA_OFF + (uint32_t)((wrow * 32 + a_r) * LDA + a_kb) * 2;
    const uint32_t bB = sb + WB_OFF + (uint32_t)((wcol * 32 + b_n) * LDA + b_kb) * 2;

    const int g = lane >> 2, t4 = lane & 3;

    float acc[2][4][4];
#pragma unroll
    for (int mi = 0; mi < 2; ++mi)
#pragma unroll
        for (int ni = 0; ni < 4; ++ni)
#pragma unroll
            for (int r = 0; r < 4; ++r) acc[mi][ni][r] = 0.f;

    // ---------------- GEMM1 over NCH chunks ---------------------------------
    for (int c = 0; c < NCH; ++c) {
        {   // W chunk copy (69632 B = 4352 float4)
            const float4* src = (const float4*)(gW + c * CHUNK_HALVES);
            float4* dst = (float4*)(smem + WB_OFF);
#pragma unroll
            for (int t = 0; t < 9; ++t) {
                int i = t * 512 + tid;
                if (i < 4352) dst[i] = src[i];
            }
        }
        {   // X gather + split (4 threads per row, 32 cols each)
            const int row = tid >> 2, q = tid & 3;
            const bool ok = row < valid;
            const float* src;
            if (EDGE) {
                if (c == 0)      src = nf + (size_t)((int*)(smem + SIDX_OFF))[row] * 128;
                else if (c == 1) src = nf + (size_t)((int*)(smem + RIDX_OFF))[row] * 128;
                else             src = ef + (size_t)(base + row) * 128;
            } else {
                src = (c ? g_agg : nf) + (size_t)(base + row) * 128;
            }
            src += q * 32;
            char* hi_t = smem + XA_OFF;
            char* lo_t = hi_t + TILE_BYTES;
            const uint32_t ro = (uint32_t)(row * LDA + q * 32) * 2;
#pragma unroll
            for (int j = 0; j < 8; ++j) {
                float4 v = ok ? ((const float4*)src)[j] : make_float4(0.f, 0.f, 0.f, 0.f);
                uint32_t l0, l1;
                uint32_t h0 = split2(v.x, v.y, l0);
                uint32_t h1 = split2(v.z, v.w, l1);
                *(uint32_t*)(hi_t + ro + j * 8) = h0;
                *(uint32_t*)(hi_t + ro + j * 8 + 4) = h1;
                *(uint32_t*)(lo_t + ro + j * 8) = l0;
                *(uint32_t*)(lo_t + ro + j * 8 + 4) = l1;
            }
        }
        __syncthreads();
        compute_chunk(acc, aB, bB);
        __syncthreads();
    }

    // ---------------- epilogue 1: h = relu(y1+b1) -> H tiles; load W2 --------
    {
        const float* s_b1 = (const float*)(smem + BIAS1_OFF);
        char* hi_t = smem + XA_OFF;
        char* lo_t = hi_t + TILE_BYTES;
#pragma unroll
        for (int mi = 0; mi < 2; ++mi) {
            const int r0 = wrow * 32 + mi * 16 + g, r1 = r0 + 8;
#pragma unroll
            for (int ni = 0; ni < 4; ++ni) {
                const int col = wcol * 32 + ni * 8 + t4 * 2;
                const float ba = s_b1[col], bb = s_b1[col + 1];
                float v0 = fmaxf(acc[mi][ni][0] + ba, 0.f);
                float v1 = fmaxf(acc[mi][ni][1] + bb, 0.f);
                float v2 = fmaxf(acc[mi][ni][2] + ba, 0.f);
                float v3 = fmaxf(acc[mi][ni][3] + bb, 0.f);
                uint32_t lo0, lo1;
                uint32_t h0 = split2(v0, v1, lo0);
                uint32_t h1 = split2(v2, v3, lo1);
                const uint32_t o0 = (uint32_t)(r0 * LDA + col) * 2;
                const uint32_t o1 = (uint32_t)(r1 * LDA + col) * 2;
                *(uint32_t*)(hi_t + o0) = h0;
                *(uint32_t*)(lo_t + o0) = lo0;
                *(uint32_t*)(hi_t + o1) = h1;
                *(uint32_t*)(lo_t + o1) = lo1;
            }
        }
        const float4* src = (const float4*)(gW + NCH * CHUNK_HALVES);
        float4* dst = (float4*)(smem + WB_OFF);
#pragma unroll
        for (int t = 0; t < 9; ++t) {
            int i = t * 512 + tid;
            if (i < 4352) dst[i] = src[i];
        }
    }
    __syncthreads();

    // ---------------- GEMM2 --------------------------------------------------
    float acc2[2][4][4];
#pragma unroll
    for (int mi = 0; mi < 2; ++mi)
#pragma unroll
        for (int ni = 0; ni < 4; ++ni)
#pragma unroll
            for (int r = 0; r < 4; ++r) acc2[mi][ni][r] = 0.f;
    compute_chunk(acc2, aB, bB);

    // ---------------- epilogue 2: LayerNorm + residual + scatter ------------
    {
        const float* s_b2 = (const float*)(smem + BIAS2_OFF);
        float s[2][2] = {{0.f, 0.f}, {0.f, 0.f}};
        float ss[2][2] = {{0.f, 0.f}, {0.f, 0.f}};
#pragma unroll
        for (int mi = 0; mi < 2; ++mi)
#pragma unroll
            for (int ni = 0; ni < 4; ++ni) {
                const int col = wcol * 32 + ni * 8 + t4 * 2;
                const float ba = s_b2[col], bb = s_b2[col + 1];
                float y0 = acc2[mi][ni][0] + ba, y1 = acc2[mi][ni][1] + bb;
                float y2 = acc2[mi][ni][2] + ba, y3 = acc2[mi][ni][3] + bb;
                acc2[mi][ni][0] = y0; acc2[mi][ni][1] = y1;
                acc2[mi][ni][2] = y2; acc2[mi][ni][3] = y3;
                s[mi][0] += y0 + y1; ss[mi][0] += y0 * y0 + y1 * y1;
                s[mi][1] += y2 + y3; ss[mi][1] += y2 * y2 + y3 * y3;
            }
#pragma unroll
        for (int off = 1; off <= 2; off <<= 1)
#pragma unroll
            for (int mi = 0; mi < 2; ++mi)
#pragma unroll
                for (int h = 0; h < 2; ++h) {
                    s[mi][h] += __shfl_xor_sync(0xffffffffu, s[mi][h], off);
                    ss[mi][h] += __shfl_xor_sync(0xffffffffu, ss[mi][h], off);
                }
        float2* part = (float2*)(smem + PART_OFF);
        if (t4 == 0)
#pragma unroll
            for (int mi = 0; mi < 2; ++mi)
#pragma unroll
                for (int h = 0; h < 2; ++h) {
                    const int row = wrow * 32 + mi * 16 + g + h * 8;
                    part[row * 4 + wcol] = make_float2(s[mi][h], ss[mi][h]);
                }
        __syncthreads();

        const float* s_g = (const float*)(smem + GAM_OFF);
        const float* s_bb = (const float*)(smem + BET_OFF);
#pragma unroll
        for (int mi = 0; mi < 2; ++mi)
#pragma unroll
            for (int h = 0; h < 2; ++h) {
                const int row = wrow * 32 + mi * 16 + g + h * 8;
                if (row >= valid) continue;
                float2 p0 = part[row * 4], p1 = part[row * 4 + 1];
                float2 p2 = part[row * 4 + 2], p3 = part[row * 4 + 3];
                const float mu = (p0.x + p1.x + p2.x + p3.x) * (1.f / 128.f);
                const float var =
                    (p0.y + p1.y + p2.y + p3.y) * (1.f / 128.f) - mu * mu;
                const float inv = rsqrtf(var + LN_EPS);
                const size_t gro = (size_t)(base + row) * 128;
                const float* res = (EDGE ? ef : nf) + gro;
                float* op = out + gro;
                float* ap = nullptr;
                if (EDGE) {
                    const int rv = ((int*)(smem + RIDX_OFF))[row];
                    ap = g_agg + (size_t)rv * 128;
                }
#pragma unroll
                for (int ni = 0; ni < 4; ++ni) {
                    const int col = wcol * 32 + ni * 8 + t4 * 2;
                    const float y0 = acc2[mi][ni][h * 2];
                    const float y1 = acc2[mi][ni][h * 2 + 1];
                    const float m0 = (y0 - mu) * inv * s_g[col] + s_bb[col];
                    const float m1 = (y1 - mu) * inv * s_g[col + 1] + s_bb[col + 1];
                    if (EDGE) red_add_v2(ap + col, m0, m1);
                    float2 r2 = *(const float2*)(res + col);
                    *(float2*)(op + col) = make_float2(m0 + r2.x, m1 + r2.y);
                }
            }
    }
}

// ---------------------------------------------------------------------------
extern "C" void kernel_launch(void* const* d_in, const int* in_sizes, int n_in,
                              void* d_out, int out_size) {
    const float* nf  = (const float*)d_in[0];
    const float* ef  = (const float*)d_in[1];
    const int*   snd = (const int*)d_in[2];
    const int*   rcv = (const int*)d_in[3];
    const float* We1 = (const float*)d_in[4];
    const float* be1 = (const float*)d_in[5];
    const float* We2 = (const float*)d_in[6];
    const float* be2 = (const float*)d_in[7];
    const float* ge  = (const float*)d_in[8];
    const float* bbe = (const float*)d_in[9];
    const float* Wn1 = (const float*)d_in[10];
    const float* bn1 = (const float*)d_in[11];
    const float* Wn2 = (const float*)d_in[12];
    const float* bn2 = (const float*)d_in[13];
    const float* gn  = (const float*)d_in[14];
    const float* bbn = (const float*)d_in[15];

    float* out_nodes = (float*)d_out;
    float* out_edges = out_nodes + (size_t)N_NODES * 128;

    cudaFuncSetAttribute(gnb_kernel<3, true>,
                         cudaFuncAttributeMaxDynamicSharedMemorySize, SMEM_TOTAL);
    cudaFuncSetAttribute(gnb_kernel<2, false>,
                         cudaFuncAttributeMaxDynamicSharedMemorySize, SMEM_TOTAL);

    prep_kernel<<<(7 * 16384 + 255) / 256, 256>>>(We1, We2, Wn1, Wn2);
    zero_agg_kernel<<<(N_NODES * 128 / 4) / 256, 256>>>();

    const int eblocks = (N_EDGES + 127) / 128;  // 4688
    gnb_kernel<3, true><<<eblocks, 512, SMEM_TOTAL>>>(
        nf, ef, snd, rcv, be1, be2, ge, bbe, out_edges);

    const int nblocks = (N_NODES + 127) / 128;  // 391
    gnb_kernel<2, false><<<nblocks, 512, SMEM_TOTAL>>>(
        nf, nullptr, nullptr, nullptr, bn1, bn2, gn, bbn, out_nodes);
}

// round 5
// speedup vs baseline: 2.1796x; 1.1252x over previous
#include <cuda_runtime.h>
#include <cuda_bf16.h>
#include <cstdint>

#define N_NODES 50000
#define N_EDGES 600000
#define LN_EPS 1e-5f

#define LDA 136                         // halves per row (16B pad: conflict-free ldmatrix)
#define XT_BYTES (64 * LDA * 2)         // 17408  (X tile: 64 rows)
#define WT_BYTES (128 * LDA * 2)        // 34816  (W tile: 128 rows)
#define WCHUNK_HALVES (2 * 128 * LDA)   // hi + lo = 34816 halves
#define WCHUNK_BYTES  (2 * WT_BYTES)    // 69632

// ---------------- device-global scratch (no allocations allowed) ------------
__device__ float g_agg[N_NODES * 128];
// Pre-split, pre-transposed weights as B[n][k] (row-major over k), padded LDA.
// Edge: chunks 0-2 = We1 (K=384), 3 = We2. Node: 0-1 = Wn1 (K=256), 2 = Wn2.
__device__ __nv_bfloat16 g_We[4 * WCHUNK_HALVES];
__device__ __nv_bfloat16 g_Wn[3 * WCHUNK_HALVES];

// ---------------- smem layout (bytes) ---------------------------------------
#define XA_OFF    0                     // X/H tile: hi(17408) + lo(17408)
#define WB_OFF    34816                 // W tile: hi(34816) + lo(34816)
#define BIAS1_OFF 104448
#define BIAS2_OFF 104960
#define GAM_OFF   105472
#define BET_OFF   105984
#define SIDX_OFF  106496                // 64 ints
#define RIDX_OFF  106752
#define PART_OFF  107008                // float2[64][4] = 2048
#define SMEM_TOTAL 109056

// ---------------- helpers ----------------------------------------------------
__device__ __forceinline__ uint32_t smem_u32(const void* p) {
    uint32_t a;
    asm("{ .reg .u64 t; cvta.to.shared.u64 t, %1; cvt.u32.u64 %0, t; }"
        : "=r"(a) : "l"(p));
    return a;
}
__device__ __forceinline__ void ldsm4(uint32_t (&r)[4], uint32_t a) {
    asm volatile("ldmatrix.sync.aligned.m8n8.x4.shared.b16 {%0,%1,%2,%3}, [%4];"
                 : "=r"(r[0]), "=r"(r[1]), "=r"(r[2]), "=r"(r[3]) : "r"(a));
}
__device__ __forceinline__ void mma16816(float (&d)[4], const uint32_t (&a)[4],
                                         uint32_t b0, uint32_t b1) {
    asm volatile(
        "mma.sync.aligned.m16n8k16.row.col.f32.bf16.bf16.f32 "
        "{%0,%1,%2,%3}, {%4,%5,%6,%7}, {%8,%9}, {%0,%1,%2,%3};"
        : "+f"(d[0]), "+f"(d[1]), "+f"(d[2]), "+f"(d[3])
        : "r"(a[0]), "r"(a[1]), "r"(a[2]), "r"(a[3]), "r"(b0), "r"(b1));
}
__device__ __forceinline__ void red_add_v2(float* p, float a, float b) {
    asm volatile("red.global.add.v2.f32 [%0], {%1, %2};"
                 :: "l"(p), "f"(a), "f"(b) : "memory");
}
__device__ __forceinline__ void cp_async16(uint32_t saddr, const void* gaddr) {
    asm volatile("cp.async.cg.shared.global [%0], [%1], 16;"
                 :: "r"(saddr), "l"(gaddr) : "memory");
}
#define CP_COMMIT() asm volatile("cp.async.commit_group;" ::: "memory")
#define CP_WAIT0()  asm volatile("cp.async.wait_group 0;" ::: "memory")

// split fp32 pair -> packed bf16x2 hi (ret) and lo (out param)
__device__ __forceinline__ uint32_t split2(float a, float b, uint32_t& lo) {
    __nv_bfloat16 ha = __float2bfloat16(a), hb = __float2bfloat16(b);
    __nv_bfloat16 la = __float2bfloat16(a - __bfloat162float(ha));
    __nv_bfloat16 lb = __float2bfloat16(b - __bfloat162float(hb));
    lo = ((uint32_t)__bfloat16_as_ushort(lb) << 16) | __bfloat16_as_ushort(la);
    return ((uint32_t)__bfloat16_as_ushort(hb) << 16) | __bfloat16_as_ushort(ha);
}

// One 64x128x128 chunk, warp tile 32x32: acc += (Xhi+Xlo)(Whi+Wlo), 3-pass bf16.
__device__ __forceinline__ void compute_chunk(float (&acc)[2][4][4],
                                              uint32_t aB, uint32_t bB) {
#pragma unroll
    for (int ks = 0; ks < 8; ++ks) {
        const uint32_t ko = ks * 32;  // 16 halves * 2 bytes
        uint32_t ah[2][4], al[2][4], bh[2][4], bl[2][4];
        ldsm4(ah[0], aB + ko);
        ldsm4(ah[1], aB + 16 * LDA * 2 + ko);
        ldsm4(al[0], aB + XT_BYTES + ko);
        ldsm4(al[1], aB + XT_BYTES + 16 * LDA * 2 + ko);
        ldsm4(bh[0], bB + ko);
        ldsm4(bh[1], bB + 16 * LDA * 2 + ko);
        ldsm4(bl[0], bB + WT_BYTES + ko);
        ldsm4(bl[1], bB + WT_BYTES + 16 * LDA * 2 + ko);
        // pass 1: hi x hi  (8 independent MMAs)
#pragma unroll
        for (int mi = 0; mi < 2; ++mi)
#pragma unroll
            for (int nj = 0; nj < 2; ++nj) {
                mma16816(acc[mi][2 * nj],     ah[mi], bh[nj][0], bh[nj][1]);
                mma16816(acc[mi][2 * nj + 1], ah[mi], bh[nj][2], bh[nj][3]);
            }
        // pass 2: lo x hi
#pragma unroll
        for (int mi = 0; mi < 2; ++mi)
#pragma unroll
            for (int nj = 0; nj < 2; ++nj) {
                mma16816(acc[mi][2 * nj],     al[mi], bh[nj][0], bh[nj][1]);
                mma16816(acc[mi][2 * nj + 1], al[mi], bh[nj][2], bh[nj][3]);
            }
        // pass 3: hi x lo
#pragma unroll
        for (int mi = 0; mi < 2; ++mi)
#pragma unroll
            for (int nj = 0; nj < 2; ++nj) {
                mma16816(acc[mi][2 * nj],     ah[mi], bl[nj][0], bl[nj][1]);
                mma16816(acc[mi][2 * nj + 1], ah[mi], bl[nj][2], bl[nj][3]);
            }
    }
}

// ---------------- utility kernels -------------------------------------------
__global__ void zero_agg_kernel() {
    int i = blockIdx.x * blockDim.x + threadIdx.x;
    ((float4*)g_agg)[i] = make_float4(0.f, 0.f, 0.f, 0.f);
}

// Split + transpose weights into g_We / g_Wn as B[n][k] hi/lo, LDA-padded.
__global__ void prep_kernel(const float* __restrict__ We1, const float* __restrict__ We2,
                            const float* __restrict__ Wn1, const float* __restrict__ Wn2) {
    int idx = blockIdx.x * blockDim.x + threadIdx.x;
    if (idx >= 7 * 16384) return;
    int g = idx >> 14;   // chunk 0..6
    int i = idx & 16383;
    int n = i >> 7;      // 0..127
    int k = i & 127;
    float v;
    __nv_bfloat16* basep;
    if (g < 4) {
        basep = g_We + g * WCHUNK_HALVES;
        v = (g < 3) ? We1[(g * 128 + k) * 128 + n] : We2[k * 128 + n];
    } else {
        int gn = g - 4;
        basep = g_Wn + gn * WCHUNK_HALVES;
        v = (gn < 2) ? Wn1[(gn * 128 + k) * 128 + n] : Wn2[k * 128 + n];
    }
    __nv_bfloat16 hi = __float2bfloat16(v);
    __nv_bfloat16 lo = __float2bfloat16(v - __bfloat162float(hi));
    basep[n * LDA + k] = hi;
    basep[128 * LDA + n * LDA + k] = lo;
}

// ---------------- main fused tile kernel -------------------------------------
// 256 threads, 2 CTAs/SM, 2x4 warp grid, warp tile 32x32, M tile = 64.
// EDGE: X = [nf[snd] | nf[rcv] | ef] (NCH=3 chunks of K=128); scatter to g_agg.
// NODE: X = [nf | g_agg] (NCH=2).
template <int NCH, bool EDGE>
__global__ void __launch_bounds__(256, 2)
gnb_kernel(const float* __restrict__ nf, const float* __restrict__ ef,
           const int* __restrict__ snd, const int* __restrict__ rcv,
           const float* __restrict__ b1, const float* __restrict__ b2,
           const float* __restrict__ gam, const float* __restrict__ bet,
           float* __restrict__ out) {
    extern __shared__ char smem[];
    const uint32_t sb = smem_u32(smem);
    const int tid = threadIdx.x, lane = tid & 31, wid = tid >> 5;
    const int wrow = wid >> 2, wcol = wid & 3;
    const int base = blockIdx.x * 64;
    const int valid = min(64, (EDGE ? N_EDGES : N_NODES) - base);
    const __nv_bfloat16* gW = EDGE ? g_We : g_Wn;

    if (tid < 128) {
        ((float*)(smem + BIAS1_OFF))[tid] = b1[tid];
        ((float*)(smem + BIAS2_OFF))[tid] = b2[tid];
        ((float*)(smem + GAM_OFF))[tid] = gam[tid];
        ((float*)(smem + BET_OFF))[tid] = bet[tid];
    }
    if (EDGE && tid < 64) {
        ((int*)(smem + SIDX_OFF))[tid] = (tid < valid) ? snd[base + tid] : 0;
        ((int*)(smem + RIDX_OFF))[tid] = (tid < valid) ? rcv[base + tid] : 0;
    }
    __syncthreads();

    // ldmatrix lane addressing
    const int a_r = lane & 15;
    const int a_kb = (lane >> 4) << 3;
    const int b_n = (lane & 7) + ((lane >> 4) << 3);
    const int b_kb = ((lane >> 3) & 1) << 3;
    const uint32_t aB = sb + XA_OFF + (uint32_t)((wrow * 32 + a_r) * LDA + a_kb) * 2;
    const uint32_t bB = sb + WB_OFF + (uint32_t)((wcol * 32 + b_n) * LDA + b_kb) * 2;

    const int g = lane >> 2, t4 = lane & 3;

    float acc[2][4][4];
#pragma unroll
    for (int mi = 0; mi < 2; ++mi)
#pragma unroll
        for (int ni = 0; ni < 4; ++ni)
#pragma unroll
            for (int r = 0; r < 4; ++r) acc[mi][ni][r] = 0.f;

    // ---------------- GEMM1 over NCH chunks ---------------------------------
    for (int c = 0; c < NCH; ++c) {
        // async W chunk copy (69632 B = 4352 x 16B, 17 per thread)
        {
            const char* src = (const char*)(gW + c * WCHUNK_HALVES);
#pragma unroll
            for (int t = 0; t < 17; ++t) {
                const int i = t * 256 + tid;
                cp_async16(sb + WB_OFF + i * 16, src + i * 16);
            }
            CP_COMMIT();
        }
        // X gather + split (4 threads per row, 32 cols each)
        {
            const int row = tid >> 2, q = tid & 3;
            const bool ok = row < valid;
            const float* src;
            if (EDGE) {
                if (c == 0)      src = nf + (size_t)((int*)(smem + SIDX_OFF))[row] * 128;
                else if (c == 1) src = nf + (size_t)((int*)(smem + RIDX_OFF))[row] * 128;
                else             src = ef + (size_t)(base + row) * 128;
            } else {
                src = (c ? g_agg : nf) + (size_t)(base + row) * 128;
            }
            src += q * 32;
            char* hi_t = smem + XA_OFF;
            char* lo_t = hi_t + XT_BYTES;
            const uint32_t ro = (uint32_t)(row * LDA + q * 32) * 2;
#pragma unroll
            for (int j = 0; j < 8; ++j) {
                float4 v = ok ? ((const float4*)src)[j] : make_float4(0.f, 0.f, 0.f, 0.f);
                uint32_t l0, l1;
                uint32_t h0 = split2(v.x, v.y, l0);
                uint32_t h1 = split2(v.z, v.w, l1);
                *(uint32_t*)(hi_t + ro + j * 8) = h0;
                *(uint32_t*)(hi_t + ro + j * 8 + 4) = h1;
                *(uint32_t*)(lo_t + ro + j * 8) = l0;
                *(uint32_t*)(lo_t + ro + j * 8 + 4) = l1;
            }
        }
        CP_WAIT0();
        __syncthreads();
        compute_chunk(acc, aB, bB);
        __syncthreads();
    }

    // ---------------- epilogue 1: h = relu(y1+b1) -> H tiles; load W2 --------
    {
        const char* src = (const char*)(gW + NCH * WCHUNK_HALVES);
#pragma unroll
        for (int t = 0; t < 17; ++t) {
            const int i = t * 256 + tid;
            cp_async16(sb + WB_OFF + i * 16, src + i * 16);
        }
        CP_COMMIT();

        const float* s_b1 = (const float*)(smem + BIAS1_OFF);
        char* hi_t = smem + XA_OFF;
        char* lo_t = hi_t + XT_BYTES;
#pragma unroll
        for (int mi = 0; mi < 2; ++mi) {
            const int r0 = wrow * 32 + mi * 16 + g, r1 = r0 + 8;
#pragma unroll
            for (int ni = 0; ni < 4; ++ni) {
                const int col = wcol * 32 + ni * 8 + t4 * 2;
                const float ba = s_b1[col], bb = s_b1[col + 1];
                float v0 = fmaxf(acc[mi][ni][0] + ba, 0.f);
                float v1 = fmaxf(acc[mi][ni][1] + bb, 0.f);
                float v2 = fmaxf(acc[mi][ni][2] + ba, 0.f);
                float v3 = fmaxf(acc[mi][ni][3] + bb, 0.f);
                uint32_t lo0, lo1;
                uint32_t h0 = split2(v0, v1, lo0);
                uint32_t h1 = split2(v2, v3, lo1);
                const uint32_t o0 = (uint32_t)(r0 * LDA + col) * 2;
                const uint32_t o1 = (uint32_t)(r1 * LDA + col) * 2;
                *(uint32_t*)(hi_t + o0) = h0;
                *(uint32_t*)(lo_t + o0) = lo0;
                *(uint32_t*)(hi_t + o1) = h1;
                *(uint32_t*)(lo_t + o1) = lo1;
            }
        }
        CP_WAIT0();
    }
    __syncthreads();

    // ---------------- GEMM2 --------------------------------------------------
    float acc2[2][4][4];
#pragma unroll
    for (int mi = 0; mi < 2; ++mi)
#pragma unroll
        for (int ni = 0; ni < 4; ++ni)
#pragma unroll
            for (int r = 0; r < 4; ++r) acc2[mi][ni][r] = 0.f;
    compute_chunk(acc2, aB, bB);

    // ---------------- epilogue 2: LayerNorm + residual + scatter ------------
    {
        const float* s_b2 = (const float*)(smem + BIAS2_OFF);
        float s[2][2] = {{0.f, 0.f}, {0.f, 0.f}};
        float ss[2][2] = {{0.f, 0.f}, {0.f, 0.f}};
#pragma unroll
        for (int mi = 0; mi < 2; ++mi)
#pragma unroll
            for (int ni = 0; ni < 4; ++ni) {
                const int col = wcol * 32 + ni * 8 + t4 * 2;
                const float ba = s_b2[col], bb = s_b2[col + 1];
                float y0 = acc2[mi][ni][0] + ba, y1 = acc2[mi][ni][1] + bb;
                float y2 = acc2[mi][ni][2] + ba, y3 = acc2[mi][ni][3] + bb;
                acc2[mi][ni][0] = y0; acc2[mi][ni][1] = y1;
                acc2[mi][ni][2] = y2; acc2[mi][ni][3] = y3;
                s[mi][0] += y0 + y1; ss[mi][0] += y0 * y0 + y1 * y1;
                s[mi][1] += y2 + y3; ss[mi][1] += y2 * y2 + y3 * y3;
            }
#pragma unroll
        for (int off = 1; off <= 2; off <<= 1)
#pragma unroll
            for (int mi = 0; mi < 2; ++mi)
#pragma unroll
                for (int h = 0; h < 2; ++h) {
                    s[mi][h] += __shfl_xor_sync(0xffffffffu, s[mi][h], off);
                    ss[mi][h] += __shfl_xor_sync(0xffffffffu, ss[mi][h], off);
                }
        float2* part = (float2*)(smem + PART_OFF);
        if (t4 == 0)
#pragma unroll
            for (int mi = 0; mi < 2; ++mi)
#pragma unroll
                for (int h = 0; h < 2; ++h) {
                    const int row = wrow * 32 + mi * 16 + g + h * 8;
                    part[row * 4 + wcol] = make_float2(s[mi][h], ss[mi][h]);
                }
        __syncthreads();

        const float* s_g = (const float*)(smem + GAM_OFF);
        const float* s_bb = (const float*)(smem + BET_OFF);
#pragma unroll
        for (int mi = 0; mi < 2; ++mi)
#pragma unroll
            for (int h = 0; h < 2; ++h) {
                const int row = wrow * 32 + mi * 16 + g + h * 8;
                if (row >= valid) continue;
                float2 p0 = part[row * 4], p1 = part[row * 4 + 1];
                float2 p2 = part[row * 4 + 2], p3 = part[row * 4 + 3];
                const float mu = (p0.x + p1.x + p2.x + p3.x) * (1.f / 128.f);
                const float var =
                    (p0.y + p1.y + p2.y + p3.y) * (1.f / 128.f) - mu * mu;
                const float inv = rsqrtf(var + LN_EPS);
                const size_t gro = (size_t)(base + row) * 128;
                const float* res = (EDGE ? ef : nf) + gro;
                float* op = out + gro;
                float* ap = nullptr;
                if (EDGE) {
                    const int rv = ((int*)(smem + RIDX_OFF))[row];
                    ap = g_agg + (size_t)rv * 128;
                }
#pragma unroll
                for (int ni = 0; ni < 4; ++ni) {
                    const int col = wcol * 32 + ni * 8 + t4 * 2;
                    const float y0 = acc2[mi][ni][h * 2];
                    const float y1 = acc2[mi][ni][h * 2 + 1];
                    const float m0 = (y0 - mu) * inv * s_g[col] + s_bb[col];
                    const float m1 = (y1 - mu) * inv * s_g[col + 1] + s_bb[col + 1];
                    if (EDGE) red_add_v2(ap + col, m0, m1);
                    float2 r2 = *(const float2*)(res + col);
                    *(float2*)(op + col) = make_float2(m0 + r2.x, m1 + r2.y);
                }
            }
    }
}

// ---------------------------------------------------------------------------
extern "C" void kernel_launch(void* const* d_in, const int* in_sizes, int n_in,
                              void* d_out, int out_size) {
    const float* nf  = (const float*)d_in[0];
    const float* ef  = (const float*)d_in[1];
    const int*   snd = (const int*)d_in[2];
    const int*   rcv = (const int*)d_in[3];
    const float* We1 = (const float*)d_in[4];
    const float* be1 = (const float*)d_in[5];
    const float* We2 = (const float*)d_in[6];
    const float* be2 = (const float*)d_in[7];
    const float* ge  = (const float*)d_in[8];
    const float* bbe = (const float*)d_in[9];
    const float* Wn1 = (const float*)d_in[10];
    const float* bn1 = (const float*)d_in[11];
    const float* Wn2 = (const float*)d_in[12];
    const float* bn2 = (const float*)d_in[13];
    const float* gn  = (const float*)d_in[14];
    const float* bbn = (const float*)d_in[15];

    float* out_nodes = (float*)d_out;
    float* out_edges = out_nodes + (size_t)N_NODES * 128;

    cudaFuncSetAttribute(gnb_kernel<3, true>,
                         cudaFuncAttributeMaxDynamicSharedMemorySize, SMEM_TOTAL);
    cudaFuncSetAttribute(gnb_kernel<2, false>,
                         cudaFuncAttributeMaxDynamicSharedMemorySize, SMEM_TOTAL);

    prep_kernel<<<(7 * 16384 + 255) / 256, 256>>>(We1, We2, Wn1, Wn2);
    zero_agg_kernel<<<(N_NODES * 128 / 4) / 256, 256>>>();

    const int eblocks = (N_EDGES + 63) / 64;  // 9375
    gnb_kernel<3, true><<<eblocks, 256, SMEM_TOTAL>>>(
        nf, ef, snd, rcv, be1, be2, ge, bbe, out_edges);

    const int nblocks = (N_NODES + 63) / 64;  // 782
    gnb_kernel<2, false><<<nblocks, 256, SMEM_TOTAL>>>(
        nf, nullptr, nullptr, nullptr, bn1, bn2, gn, bbn, out_nodes);
}

// round 7
// speedup vs baseline: 2.6881x; 1.2333x over previous
#include <cuda_runtime.h>
#include <cuda_bf16.h>
#include <cstdint>

#define N_NODES 50000
#define N_EDGES 600000
#define LN_EPS 1e-5f

// ---------------- device-global scratch (no allocations allowed) ------------
__device__ float g_agg[N_NODES * 128];
__device__ __nv_bfloat16 g_nf_hi[N_NODES * 128];
__device__ __nv_bfloat16 g_nf_lo[N_NODES * 128];
__device__ __nv_bfloat16 g_ef_hi[(size_t)N_EDGES * 128];
__device__ __nv_bfloat16 g_ef_lo[(size_t)N_EDGES * 128];
__device__ __nv_bfloat16 g_ag_hi[N_NODES * 128];
__device__ __nv_bfloat16 g_ag_lo[N_NODES * 128];
// Weights per K-64 subchunk: [sc][hi 8192 | lo 8192] halves, B[n][k64] layout.
// Edge: sc 0-5 = We1 (K=384), 6-7 = We2. Node: sc 0-3 = Wn1, 4-5 = Wn2.
__device__ __nv_bfloat16 g_We[8 * 16384];
__device__ __nv_bfloat16 g_Wn[6 * 16384];

// ---------------- smem layout (bytes) ---------------------------------------
// X sub-tile buf: 64 rows x 128B, hi[0,8192) lo[8192,16384). Two bufs.
// W sub-tile buf: 128 rows x 128B, hi[0,16384) lo[16384,32768). Two bufs.
#define XB(i)     ((uint32_t)(i) * 16384u)
#define WB(i)     (32768u + (uint32_t)(i) * 32768u)
#define BIAS1_OFF 98304
#define BIAS2_OFF 98816
#define GAM_OFF   99328
#define BET_OFF   99840
#define SIDX_OFF  100352
#define RIDX_OFF  100608
#define PART_OFF  100864
#define SMEM_TOTAL 102912

// ---------------- helpers ----------------------------------------------------
__device__ __forceinline__ uint32_t smem_u32(const void* p) {
    uint32_t a;
    asm("{ .reg .u64 t; cvta.to.shared.u64 t, %1; cvt.u32.u64 %0, t; }"
        : "=r"(a) : "l"(p));
    return a;
}
__device__ __forceinline__ void ldsm4(uint32_t (&r)[4], uint32_t a) {
    asm volatile("ldmatrix.sync.aligned.m8n8.x4.shared.b16 {%0,%1,%2,%3}, [%4];"
                 : "=r"(r[0]), "=r"(r[1]), "=r"(r[2]), "=r"(r[3]) : "r"(a));
}
__device__ __forceinline__ void mma16816(float (&d)[4], const uint32_t (&a)[4],
                                         uint32_t b0, uint32_t b1) {
    asm volatile(
        "mma.sync.aligned.m16n8k16.row.col.f32.bf16.bf16.f32 "
        "{%0,%1,%2,%3}, {%4,%5,%6,%7}, {%8,%9}, {%0,%1,%2,%3};"
        : "+f"(d[0]), "+f"(d[1]), "+f"(d[2]), "+f"(d[3])
        : "r"(a[0]), "r"(a[1]), "r"(a[2]), "r"(a[3]), "r"(b0), "r"(b1));
}
__device__ __forceinline__ void red_add_v2(float* p, float a, float b) {
    asm volatile("red.global.add.v2.f32 [%0], {%1, %2};"
                 :: "l"(p), "f"(a), "f"(b) : "memory");
}
__device__ __forceinline__ void cp_async16(uint32_t d, const void* s) {
    asm volatile("cp.async.cg.shared.global [%0], [%1], 16;"
                 :: "r"(d), "l"(s) : "memory");
}
__device__ __forceinline__ void cp_async16z(uint32_t d, const void* s, uint32_t sz) {
    asm volatile("cp.async.cg.shared.global [%0], [%1], 16, %2;"
                 :: "r"(d), "l"(s), "r"(sz) : "memory");
}
#define CP_COMMIT() asm volatile("cp.async.commit_group;" ::: "memory")

// split fp32 pair -> packed bf16x2 hi (ret) and lo (out param)
__device__ __forceinline__ uint32_t split2(float a, float b, uint32_t& lo) {
    __nv_bfloat16 ha = __float2bfloat16(a), hb = __float2bfloat16(b);
    __nv_bfloat16 la = __float2bfloat16(a - __bfloat162float(ha));
    __nv_bfloat16 lb = __float2bfloat16(b - __bfloat162float(hb));
    lo = ((uint32_t)__bfloat16_as_ushort(lb) << 16) | __bfloat16_as_ushort(la);
    return ((uint32_t)__bfloat16_as_ushort(hb) << 16) | __bfloat16_as_ushort(ha);
}

// ---------------- utility kernels (device symbols referenced in DEVICE code) -
__global__ void zero_agg_kernel() {
    int i = blockIdx.x * blockDim.x + threadIdx.x;
    ((float4*)g_agg)[i] = make_float4(0.f, 0.f, 0.f, 0.f);
}
__global__ void split_nf_kernel(const float* __restrict__ src) {
    int i = blockIdx.x * blockDim.x + threadIdx.x;   // N_NODES*32 float4s
    float4 v = ((const float4*)src)[i];
    uint32_t l0, l1;
    uint32_t h0 = split2(v.x, v.y, l0);
    uint32_t h1 = split2(v.z, v.w, l1);
    ((uint2*)g_nf_hi)[i] = make_uint2(h0, h1);
    ((uint2*)g_nf_lo)[i] = make_uint2(l0, l1);
}
__global__ void split_ef_kernel(const float* __restrict__ src) {
    int i = blockIdx.x * blockDim.x + threadIdx.x;   // N_EDGES*32 float4s
    float4 v = ((const float4*)src)[i];
    uint32_t l0, l1;
    uint32_t h0 = split2(v.x, v.y, l0);
    uint32_t h1 = split2(v.z, v.w, l1);
    ((uint2*)g_ef_hi)[i] = make_uint2(h0, h1);
    ((uint2*)g_ef_lo)[i] = make_uint2(l0, l1);
}
__global__ void split_agg_kernel() {
    int i = blockIdx.x * blockDim.x + threadIdx.x;
    float4 v = ((const float4*)g_agg)[i];
    uint32_t l0, l1;
    uint32_t h0 = split2(v.x, v.y, l0);
    uint32_t h1 = split2(v.z, v.w, l1);
    ((uint2*)g_ag_hi)[i] = make_uint2(h0, h1);
    ((uint2*)g_ag_lo)[i] = make_uint2(l0, l1);
}
__global__ void prep_w(const float* __restrict__ We1, const float* __restrict__ We2,
                       const float* __restrict__ Wn1, const float* __restrict__ Wn2) {
    int idx = blockIdx.x * blockDim.x + threadIdx.x;
    if (idx >= 114688) return;
    __nv_bfloat16* dst;
    float v;
    int n, kk;
    if (idx < 65536) {
        int sc = idx >> 13, rem = idx & 8191;
        n = rem >> 6; kk = rem & 63;
        v = (sc < 6) ? We1[(sc * 64 + kk) * 128 + n] : We2[((sc - 6) * 64 + kk) * 128 + n];
        dst = g_We + sc * 16384;
    } else {
        int j = idx - 65536;
        int sc = j >> 13, rem = j & 8191;
        n = rem >> 6; kk = rem & 63;
        v = (sc < 4) ? Wn1[(sc * 64 + kk) * 128 + n] : Wn2[((sc - 4) * 64 + kk) * 128 + n];
        dst = g_Wn + sc * 16384;
    }
    __nv_bfloat16 hi = __float2bfloat16(v);
    __nv_bfloat16 lo = __float2bfloat16(v - __bfloat162float(hi));
    dst[n * 64 + kk] = hi;
    dst[8192 + n * 64 + kk] = lo;
}

// ---------------- main fused tile kernel -------------------------------------
// 256 threads, 2 CTAs/SM, 2x4 warp grid (warp tile 32x32), M tile 64.
// Pipeline over K-64 subchunks, all X/W via cp.async from pre-split globals.
template <int S1, bool EDGE>
__global__ void __launch_bounds__(256, 2)
gnb_kernel(const float* __restrict__ nf, const float* __restrict__ ef,
           const int* __restrict__ snd, const int* __restrict__ rcv,
           const float* __restrict__ b1, const float* __restrict__ b2,
           const float* __restrict__ gam, const float* __restrict__ bet,
           float* __restrict__ out) {
    extern __shared__ char smem[];
    const uint32_t sb = smem_u32(smem);
    const int tid = threadIdx.x, lane = tid & 31, wid = tid >> 5;
    const int wrow = wid >> 2, wcol = wid & 3;
    const int base = blockIdx.x * 64;
    const int total = EDGE ? N_EDGES : N_NODES;
    const int valid = min(64, total - base);

    if (tid < 128) {
        ((float*)(smem + BIAS1_OFF))[tid] = b1[tid];
        ((float*)(smem + BIAS2_OFF))[tid] = b2[tid];
        ((float*)(smem + GAM_OFF))[tid] = gam[tid];
        ((float*)(smem + BET_OFF))[tid] = bet[tid];
    }
    if (EDGE && tid < 64) {
        ((int*)(smem + SIDX_OFF))[tid] = (tid < valid) ? snd[base + tid] : 0;
        ((int*)(smem + RIDX_OFF))[tid] = (tid < valid) ? rcv[base + tid] : 0;
    }
    __syncthreads();

    // per-lane ldsm constants (swizzled: block b at row r lives at (b ^ (r&7))*16)
    const int aHi = lane >> 4;
    const int rA = wrow * 32 + (lane & 15);
    const int xA = rA & 7;
    const uint32_t aRow = (uint32_t)rA * 128;
    const int bHi = (lane >> 3) & 1;
    const int rB = wcol * 32 + (lane & 7) + ((lane >> 4) << 3);
    const int xB = rB & 7;
    const uint32_t bRow = (uint32_t)rB * 128;
    const int g = lane >> 2, t4 = lane & 3;

    auto issueW = [&](int sc, uint32_t woff) {
        const __nv_bfloat16* gW = EDGE ? g_We : g_Wn;
#pragma unroll
        for (int p = 0; p < 8; ++p) {
            int m = p * 256 + tid;
            int hl = m >> 10, rem = m & 1023, row = rem >> 3, b = rem & 7;
            const __nv_bfloat16* src = gW + sc * 16384 + hl * 8192 + row * 64 + b * 8;
            uint32_t dst = sb + woff + (uint32_t)hl * 16384 + (uint32_t)row * 128 +
                           (uint32_t)((b ^ (row & 7)) << 4);
            cp_async16(dst, src);
        }
    };
    auto issueX = [&](int s, uint32_t xoff) {
        const int cs = s >> 1, kh = s & 1;
#pragma unroll
        for (int p = 0; p < 4; ++p) {
            int m = p * 256 + tid;
            int hl = m >> 9, rem = m & 511, row = rem >> 3, b = rem & 7;
            int gr;
            const __nv_bfloat16 *sH, *sL;
            if (EDGE) {
                if (cs == 0) {
                    gr = ((const int*)(smem + SIDX_OFF))[row];
                    sH = g_nf_hi; sL = g_nf_lo;
                } else if (cs == 1) {
                    gr = ((const int*)(smem + RIDX_OFF))[row];
                    sH = g_nf_hi; sL = g_nf_lo;
                } else {
                    gr = base + row;
                    sH = g_ef_hi; sL = g_ef_lo;
                }
            } else {
                gr = base + row;
                if (gr >= total) gr = total - 1;
                if (cs == 0) { sH = g_nf_hi; sL = g_nf_lo; }
                else         { sH = g_ag_hi; sL = g_ag_lo; }
            }
            const __nv_bfloat16* src = (hl ? sL : sH) + (size_t)gr * 128 + kh * 64 + b * 8;
            uint32_t dst = sb + xoff + (uint32_t)hl * 8192 + (uint32_t)row * 128 +
                           (uint32_t)((b ^ (row & 7)) << 4);
            cp_async16z(dst, src, (row < valid) ? 16u : 0u);
        }
    };
    // 64-wide-K subchunk compute: acc += (Xhi+Xlo)(Whi+Wlo), 3-pass, pass-major.
    auto compute_sub = [&](float (&acc)[2][4][4], uint32_t xbase, uint32_t wbase) {
#pragma unroll
        for (int ks = 0; ks < 4; ++ks) {
            const uint32_t oA = aRow + (uint32_t)((((2 * ks + aHi) ^ xA)) << 4);
            const uint32_t oB = bRow + (uint32_t)((((2 * ks + bHi) ^ xB)) << 4);
            uint32_t ah[2][4], al[2][4], bh[2][4], bl[2][4];
            ldsm4(ah[0], xbase + oA);
            ldsm4(ah[1], xbase + oA + 2048);
            ldsm4(al[0], xbase + 8192 + oA);
            ldsm4(al[1], xbase + 8192 + oA + 2048);
            ldsm4(bh[0], wbase + oB);
            ldsm4(bh[1], wbase + oB + 2048);
            ldsm4(bl[0], wbase + 16384 + oB);
            ldsm4(bl[1], wbase + 16384 + oB + 2048);
#pragma unroll
            for (int mi = 0; mi < 2; ++mi)
#pragma unroll
                for (int nj = 0; nj < 2; ++nj) {
                    mma16816(acc[mi][2 * nj],     ah[mi], bh[nj][0], bh[nj][1]);
                    mma16816(acc[mi][2 * nj + 1], ah[mi], bh[nj][2], bh[nj][3]);
                }
#pragma unroll
            for (int mi = 0; mi < 2; ++mi)
#pragma unroll
                for (int nj = 0; nj < 2; ++nj) {
                    mma16816(acc[mi][2 * nj],     al[mi], bh[nj][0], bh[nj][1]);
                    mma16816(acc[mi][2 * nj + 1], al[mi], bh[nj][2], bh[nj][3]);
                }
#pragma unroll
            for (int mi = 0; mi < 2; ++mi)
#pragma unroll
                for (int nj = 0; nj < 2; ++nj) {
                    mma16816(acc[mi][2 * nj],     ah[mi], bl[nj][0], bl[nj][1]);
                    mma16816(acc[mi][2 * nj + 1], ah[mi], bl[nj][2], bl[nj][3]);
                }
        }
    };

    float acc[2][4][4];
#pragma unroll
    for (int mi = 0; mi < 2; ++mi)
#pragma unroll
        for (int ni = 0; ni < 4; ++ni)
#pragma unroll
            for (int r = 0; r < 4; ++r) acc[mi][ni][r] = 0.f;

    // ---------------- GEMM1: pipelined over S1 subchunks --------------------
    issueX(0, XB(0));
    issueW(0, WB(0));
    CP_COMMIT();
#pragma unroll
    for (int s = 0; s < S1; ++s) {
        if (s + 1 < S1) {
            issueX(s + 1, XB((s + 1) & 1));
            issueW(s + 1, WB((s + 1) & 1));
            CP_COMMIT();
            asm volatile("cp.async.wait_group 1;" ::: "memory");
        } else {
            asm volatile("cp.async.wait_group 0;" ::: "memory");
        }
        __syncthreads();
        compute_sub(acc, sb + XB(s & 1), sb + WB(s & 1));
        __syncthreads();
    }

    // ---------------- epilogue 1: prefetch W2; h=relu(y1+b1) -> H tiles -----
    issueW(S1, WB(0));
    issueW(S1 + 1, WB(1));
    CP_COMMIT();
    {
        const float* s_b1 = (const float*)(smem + BIAS1_OFF);
#pragma unroll
        for (int mi = 0; mi < 2; ++mi) {
            const int r0 = wrow * 32 + mi * 16 + g, r1 = r0 + 8;
#pragma unroll
            for (int ni = 0; ni < 4; ++ni) {
                const int col = wcol * 32 + ni * 8 + t4 * 2;
                const float ba = s_b1[col], bb = s_b1[col + 1];
                float v0 = fmaxf(acc[mi][ni][0] + ba, 0.f);
                float v1 = fmaxf(acc[mi][ni][1] + bb, 0.f);
                float v2 = fmaxf(acc[mi][ni][2] + ba, 0.f);
                float v3 = fmaxf(acc[mi][ni][3] + bb, 0.f);
                uint32_t lo0, lo1;
                uint32_t h0 = split2(v0, v1, lo0);
                uint32_t h1 = split2(v2, v3, lo1);
                const int sub = col >> 6, kk = col & 63;
                const int bblk = kk >> 3, w2 = (kk & 7) * 2;
                char* tb = smem + sub * 16384;
                char* d0 = tb + r0 * 128 + (((bblk ^ (r0 & 7))) << 4) + w2;
                char* d1 = tb + r1 * 128 + (((bblk ^ (r1 & 7))) << 4) + w2;
                *(uint32_t*)d0 = h0;
                *(uint32_t*)(d0 + 8192) = lo0;
                *(uint32_t*)d1 = h1;
                *(uint32_t*)(d1 + 8192) = lo1;
            }
        }
    }
    asm volatile("cp.async.wait_group 0;" ::: "memory");
    __syncthreads();

    // ---------------- GEMM2: 2 subchunks (H in XB0/XB1, W2 in WB0/WB1) ------
    float acc2[2][4][4];
#pragma unroll
    for (int mi = 0; mi < 2; ++mi)
#pragma unroll
        for (int ni = 0; ni < 4; ++ni)
#pragma unroll
            for (int r = 0; r < 4; ++r) acc2[mi][ni][r] = 0.f;
    compute_sub(acc2, sb + XB(0), sb + WB(0));
    compute_sub(acc2, sb + XB(1), sb + WB(1));

    // ---------------- epilogue 2: LayerNorm + residual + scatter ------------
    {
        const float* s_b2 = (const float*)(smem + BIAS2_OFF);
        float s[2][2] = {{0.f, 0.f}, {0.f, 0.f}};
        float ss[2][2] = {{0.f, 0.f}, {0.f, 0.f}};
#pragma unroll
        for (int mi = 0; mi < 2; ++mi)
#pragma unroll
            for (int ni = 0; ni < 4; ++ni) {
                const int col = wcol * 32 + ni * 8 + t4 * 2;
                const float ba = s_b2[col], bb = s_b2[col + 1];
                float y0 = acc2[mi][ni][0] + ba, y1 = acc2[mi][ni][1] + bb;
                float y2 = acc2[mi][ni][2] + ba, y3 = acc2[mi][ni][3] + bb;
                acc2[mi][ni][0] = y0; acc2[mi][ni][1] = y1;
                acc2[mi][ni][2] = y2; acc2[mi][ni][3] = y3;
                s[mi][0] += y0 + y1; ss[mi][0] += y0 * y0 + y1 * y1;
                s[mi][1] += y2 + y3; ss[mi][1] += y2 * y2 + y3 * y3;
            }
#pragma unroll
        for (int off = 1; off <= 2; off <<= 1)
#pragma unroll
            for (int mi = 0; mi < 2; ++mi)
#pragma unroll
                for (int h = 0; h < 2; ++h) {
                    s[mi][h] += __shfl_xor_sync(0xffffffffu, s[mi][h], off);
                    ss[mi][h] += __shfl_xor_sync(0xffffffffu, ss[mi][h], off);
                }
        float2* part = (float2*)(smem + PART_OFF);
        if (t4 == 0)
#pragma unroll
            for (int mi = 0; mi < 2; ++mi)
#pragma unroll
                for (int h = 0; h < 2; ++h) {
                    const int row = wrow * 32 + mi * 16 + g + h * 8;
                    part[row * 4 + wcol] = make_float2(s[mi][h], ss[mi][h]);
                }
        __syncthreads();

        const float* s_g = (const float*)(smem + GAM_OFF);
        const float* s_bb = (const float*)(smem + BET_OFF);
#pragma unroll
        for (int mi = 0; mi < 2; ++mi)
#pragma unroll
            for (int h = 0; h < 2; ++h) {
                const int row = wrow * 32 + mi * 16 + g + h * 8;
                if (row >= valid) continue;
                float2 p0 = part[row * 4], p1 = part[row * 4 + 1];
                float2 p2 = part[row * 4 + 2], p3 = part[row * 4 + 3];
                const float mu = (p0.x + p1.x + p2.x + p3.x) * (1.f / 128.f);
                const float var =
                    (p0.y + p1.y + p2.y + p3.y) * (1.f / 128.f) - mu * mu;
                const float inv = rsqrtf(var + LN_EPS);
                const size_t gro = (size_t)(base + row) * 128;
                const float* res = (EDGE ? ef : nf) + gro;
                float* op = out + gro;
                float* ap = nullptr;
                if (EDGE) {
                    const int rv = ((const int*)(smem + RIDX_OFF))[row];
                    ap = g_agg + (size_t)rv * 128;
                }
#pragma unroll
                for (int ni = 0; ni < 4; ++ni) {
                    const int col = wcol * 32 + ni * 8 + t4 * 2;
                    const float y0 = acc2[mi][ni][h * 2];
                    const float y1 = acc2[mi][ni][h * 2 + 1];
                    const float m0 = (y0 - mu) * inv * s_g[col] + s_bb[col];
                    const float m1 = (y1 - mu) * inv * s_g[col + 1] + s_bb[col + 1];
                    if (EDGE) red_add_v2(ap + col, m0, m1);
                    float2 r2 = *(const float2*)(res + col);
                    *(float2*)(op + col) = make_float2(m0 + r2.x, m1 + r2.y);
                }
            }
    }
}

// ---------------------------------------------------------------------------
extern "C" void kernel_launch(void* const* d_in, const int* in_sizes, int n_in,
                              void* d_out, int out_size) {
    const float* nf  = (const float*)d_in[0];
    const float* ef  = (const float*)d_in[1];
    const int*   snd = (const int*)d_in[2];
    const int*   rcv = (const int*)d_in[3];
    const float* We1 = (const float*)d_in[4];
    const float* be1 = (const float*)d_in[5];
    const float* We2 = (const float*)d_in[6];
    const float* be2 = (const float*)d_in[7];
    const float* ge  = (const float*)d_in[8];
    const float* bbe = (const float*)d_in[9];
    const float* Wn1 = (const float*)d_in[10];
    const float* bn1 = (const float*)d_in[11];
    const float* Wn2 = (const float*)d_in[12];
    const float* bn2 = (const float*)d_in[13];
    const float* gn  = (const float*)d_in[14];
    const float* bbn = (const float*)d_in[15];

    float* out_nodes = (float*)d_out;
    float* out_edges = out_nodes + (size_t)N_NODES * 128;

    cudaFuncSetAttribute(gnb_kernel<6, true>,
                         cudaFuncAttributeMaxDynamicSharedMemorySize, SMEM_TOTAL);
    cudaFuncSetAttribute(gnb_kernel<4, false>,
                         cudaFuncAttributeMaxDynamicSharedMemorySize, SMEM_TOTAL);

    prep_w<<<448, 256>>>(We1, We2, Wn1, Wn2);
    split_nf_kernel<<<6250, 256>>>(nf);      // 50000*32 float4s
    split_ef_kernel<<<75000, 256>>>(ef);     // 600000*32 float4s
    zero_agg_kernel<<<6250, 256>>>();

    gnb_kernel<6, true><<<N_EDGES / 64, 256, SMEM_TOTAL>>>(
        nf, ef, snd, rcv, be1, be2, ge, bbe, out_edges);

    split_agg_kernel<<<6250, 256>>>();

    gnb_kernel<4, false><<<(N_NODES + 63) / 64, 256, SMEM_TOTAL>>>(
        nf, nullptr, nullptr, nullptr, bn1, bn2, gn, bbn, out_nodes);
}

// round 8
// speedup vs baseline: 3.4320x; 1.2768x over previous
#include <cuda_runtime.h>
#include <cuda_fp16.h>
#include <cstdint>

#define N_NODES 50000
#define N_EDGES 600000
#define LN_EPS 1e-5f

// ---------------- device-global scratch (no allocations allowed) ------------
__device__ float g_agg[N_NODES * 128];
__device__ __half g_nf_hi[N_NODES * 128];
__device__ __half g_nf_lo[N_NODES * 128];
__device__ __half g_ef_hi[(size_t)N_EDGES * 128];
__device__ __half g_ef_lo[(size_t)N_EDGES * 128];
__device__ __half g_ag_hi[N_NODES * 128];
__device__ __half g_ag_lo[N_NODES * 128];
// Weights per K-64 subchunk: [sc][8192 halves], B[n][k64] layout, fp16 (single).
// Edge: sc 0-5 = We1 (K=384), 6-7 = We2. Node: sc 0-3 = Wn1, 4-5 = Wn2.
__device__ __half g_We[8 * 8192];
__device__ __half g_Wn[6 * 8192];

// ---------------- smem layout (bytes) ---------------------------------------
// X sub-tile buf: 64 rows x 128B, hi[0,8192) lo[8192,16384). Two bufs.
// W sub-tile buf: 128 rows x 128B (fp16 single). Two bufs.
#define XB(i)     ((uint32_t)(i) * 16384u)
#define WB(i)     (32768u + (uint32_t)(i) * 16384u)
#define BIAS1_OFF 65536
#define BIAS2_OFF 66048
#define GAM_OFF   66560
#define BET_OFF   67072
#define SIDX_OFF  67584
#define RIDX_OFF  67840
#define PART_OFF  68096
#define SMEM_TOTAL 70144

// ---------------- helpers ----------------------------------------------------
__device__ __forceinline__ uint32_t smem_u32(const void* p) {
    uint32_t a;
    asm("{ .reg .u64 t; cvta.to.shared.u64 t, %1; cvt.u32.u64 %0, t; }"
        : "=r"(a) : "l"(p));
    return a;
}
__device__ __forceinline__ void ldsm4(uint32_t (&r)[4], uint32_t a) {
    asm volatile("ldmatrix.sync.aligned.m8n8.x4.shared.b16 {%0,%1,%2,%3}, [%4];"
                 : "=r"(r[0]), "=r"(r[1]), "=r"(r[2]), "=r"(r[3]) : "r"(a));
}
__device__ __forceinline__ void mma16816(float (&d)[4], const uint32_t (&a)[4],
                                         uint32_t b0, uint32_t b1) {
    asm volatile(
        "mma.sync.aligned.m16n8k16.row.col.f32.f16.f16.f32 "
        "{%0,%1,%2,%3}, {%4,%5,%6,%7}, {%8,%9}, {%0,%1,%2,%3};"
        : "+f"(d[0]), "+f"(d[1]), "+f"(d[2]), "+f"(d[3])
        : "r"(a[0]), "r"(a[1]), "r"(a[2]), "r"(a[3]), "r"(b0), "r"(b1));
}
__device__ __forceinline__ void red_add_v2(float* p, float a, float b) {
    asm volatile("red.global.add.v2.f32 [%0], {%1, %2};"
                 :: "l"(p), "f"(a), "f"(b) : "memory");
}
__device__ __forceinline__ void cp_async16(uint32_t d, const void* s) {
    asm volatile("cp.async.cg.shared.global [%0], [%1], 16;"
                 :: "r"(d), "l"(s) : "memory");
}
__device__ __forceinline__ void cp_async16z(uint32_t d, const void* s, uint32_t sz) {
    asm volatile("cp.async.cg.shared.global [%0], [%1], 16, %2;"
                 :: "r"(d), "l"(s), "r"(sz) : "memory");
}
#define CP_COMMIT() asm volatile("cp.async.commit_group;" ::: "memory")

// split fp32 pair -> packed fp16x2 hi (ret) and lo (out param)
__device__ __forceinline__ uint32_t split2h(float a, float b, uint32_t& lo) {
    __half ha = __float2half_rn(a), hb = __float2half_rn(b);
    __half la = __float2half_rn(a - __half2float(ha));
    __half lb = __float2half_rn(b - __half2float(hb));
    lo = ((uint32_t)__half_as_ushort(lb) << 16) | __half_as_ushort(la);
    return ((uint32_t)__half_as_ushort(hb) << 16) | __half_as_ushort(ha);
}

// ---------------- utility kernels (device symbols referenced in DEVICE code) -
__global__ void zero_agg_kernel() {
    int i = blockIdx.x * blockDim.x + threadIdx.x;
    ((float4*)g_agg)[i] = make_float4(0.f, 0.f, 0.f, 0.f);
}
__global__ void split_nf_kernel(const float* __restrict__ src) {
    int i = blockIdx.x * blockDim.x + threadIdx.x;   // N_NODES*32 float4s
    float4 v = ((const float4*)src)[i];
    uint32_t l0, l1;
    uint32_t h0 = split2h(v.x, v.y, l0);
    uint32_t h1 = split2h(v.z, v.w, l1);
    ((uint2*)g_nf_hi)[i] = make_uint2(h0, h1);
    ((uint2*)g_nf_lo)[i] = make_uint2(l0, l1);
}
__global__ void split_ef_kernel(const float* __restrict__ src) {
    int i = blockIdx.x * blockDim.x + threadIdx.x;   // N_EDGES*32 float4s
    float4 v = ((const float4*)src)[i];
    uint32_t l0, l1;
    uint32_t h0 = split2h(v.x, v.y, l0);
    uint32_t h1 = split2h(v.z, v.w, l1);
    ((uint2*)g_ef_hi)[i] = make_uint2(h0, h1);
    ((uint2*)g_ef_lo)[i] = make_uint2(l0, l1);
}
__global__ void split_agg_kernel() {
    int i = blockIdx.x * blockDim.x + threadIdx.x;
    float4 v = ((const float4*)g_agg)[i];
    uint32_t l0, l1;
    uint32_t h0 = split2h(v.x, v.y, l0);
    uint32_t h1 = split2h(v.z, v.w, l1);
    ((uint2*)g_ag_hi)[i] = make_uint2(h0, h1);
    ((uint2*)g_ag_lo)[i] = make_uint2(l0, l1);
}
__global__ void prep_w(const float* __restrict__ We1, const float* __restrict__ We2,
                       const float* __restrict__ Wn1, const float* __restrict__ Wn2) {
    int idx = blockIdx.x * blockDim.x + threadIdx.x;
    if (idx >= 114688) return;
    __half* dst;
    float v;
    int n, kk;
    if (idx < 65536) {
        int sc = idx >> 13, rem = idx & 8191;
        n = rem >> 6; kk = rem & 63;
        v = (sc < 6) ? We1[(sc * 64 + kk) * 128 + n] : We2[((sc - 6) * 64 + kk) * 128 + n];
        dst = g_We + sc * 8192;
    } else {
        int j = idx - 65536;
        int sc = j >> 13, rem = j & 8191;
        n = rem >> 6; kk = rem & 63;
        v = (sc < 4) ? Wn1[(sc * 64 + kk) * 128 + n] : Wn2[((sc - 4) * 64 + kk) * 128 + n];
        dst = g_Wn + sc * 8192;
    }
    dst[n * 64 + kk] = __float2half_rn(v);
}

// ---------------- main fused tile kernel -------------------------------------
// 256 threads, 3 CTAs/SM, 2x4 warp grid (warp tile 32x32), M tile 64.
// fp16 2-pass: X split hi/lo, W single fp16. acc reused between GEMM1/GEMM2.
template <int S1, bool EDGE>
__global__ void __launch_bounds__(256, 3)
gnb_kernel(const float* __restrict__ nf, const float* __restrict__ ef,
           const int* __restrict__ snd, const int* __restrict__ rcv,
           const float* __restrict__ b1, const float* __restrict__ b2,
           const float* __restrict__ gam, const float* __restrict__ bet,
           float* __restrict__ out) {
    extern __shared__ char smem[];
    const uint32_t sb = smem_u32(smem);
    const int tid = threadIdx.x, lane = tid & 31, wid = tid >> 5;
    const int wrow = wid >> 2, wcol = wid & 3;
    const int base = blockIdx.x * 64;
    const int total = EDGE ? N_EDGES : N_NODES;
    const int valid = min(64, total - base);

    if (tid < 128) {
        ((float*)(smem + BIAS1_OFF))[tid] = b1[tid];
        ((float*)(smem + BIAS2_OFF))[tid] = b2[tid];
        ((float*)(smem + GAM_OFF))[tid] = gam[tid];
        ((float*)(smem + BET_OFF))[tid] = bet[tid];
    }
    if (EDGE && tid < 64) {
        ((int*)(smem + SIDX_OFF))[tid] = (tid < valid) ? snd[base + tid] : 0;
        ((int*)(smem + RIDX_OFF))[tid] = (tid < valid) ? rcv[base + tid] : 0;
    }
    __syncthreads();

    // per-lane ldsm constants (swizzled: block b at row r lives at (b ^ (r&7))*16)
    const int aHi = lane >> 4;
    const int rA = wrow * 32 + (lane & 15);
    const int xA = rA & 7;
    const uint32_t aRow = (uint32_t)rA * 128;
    const int bHi = (lane >> 3) & 1;
    const int rB = wcol * 32 + (lane & 7) + ((lane >> 4) << 3);
    const int xB = rB & 7;
    const uint32_t bRow = (uint32_t)rB * 128;
    const int g = lane >> 2, t4 = lane & 3;

    auto issueW = [&](int sc, uint32_t woff) {
        const __half* gW = EDGE ? g_We : g_Wn;
#pragma unroll
        for (int p = 0; p < 4; ++p) {
            int m = p * 256 + tid;                  // 1024 16B chunks
            int row = m >> 3, b = m & 7;
            const __half* src = gW + sc * 8192 + row * 64 + b * 8;
            uint32_t dst = sb + woff + (uint32_t)row * 128 +
                           (uint32_t)((b ^ (row & 7)) << 4);
            cp_async16(dst, src);
        }
    };
    auto issueX = [&](int s, uint32_t xoff) {
        const int cs = s >> 1, kh = s & 1;
#pragma unroll
        for (int p = 0; p < 4; ++p) {
            int m = p * 256 + tid;
            int hl = m >> 9, rem = m & 511, row = rem >> 3, b = rem & 7;
            int gr;
            const __half *sH, *sL;
            if (EDGE) {
                if (cs == 0) {
                    gr = ((const int*)(smem + SIDX_OFF))[row];
                    sH = g_nf_hi; sL = g_nf_lo;
                } else if (cs == 1) {
                    gr = ((const int*)(smem + RIDX_OFF))[row];
                    sH = g_nf_hi; sL = g_nf_lo;
                } else {
                    gr = base + row;
                    sH = g_ef_hi; sL = g_ef_lo;
                }
            } else {
                gr = base + row;
                if (gr >= total) gr = total - 1;
                if (cs == 0) { sH = g_nf_hi; sL = g_nf_lo; }
                else         { sH = g_ag_hi; sL = g_ag_lo; }
            }
            const __half* src = (hl ? sL : sH) + (size_t)gr * 128 + kh * 64 + b * 8;
            uint32_t dst = sb + xoff + (uint32_t)hl * 8192 + (uint32_t)row * 128 +
                           (uint32_t)((b ^ (row & 7)) << 4);
            cp_async16z(dst, src, (row < valid) ? 16u : 0u);
        }
    };
    // 64-wide-K subchunk: acc += (Xhi+Xlo)*W, 2-pass fp16, pass-major.
    auto compute_sub = [&](float (&acc)[2][4][4], uint32_t xbase, uint32_t wbase) {
#pragma unroll
        for (int ks = 0; ks < 4; ++ks) {
            const uint32_t oA = aRow + (uint32_t)((((2 * ks + aHi) ^ xA)) << 4);
            const uint32_t oB = bRow + (uint32_t)((((2 * ks + bHi) ^ xB)) << 4);
            uint32_t ah[2][4], al[2][4], bh[2][4];
            ldsm4(ah[0], xbase + oA);
            ldsm4(ah[1], xbase + oA + 2048);
            ldsm4(al[0], xbase + 8192 + oA);
            ldsm4(al[1], xbase + 8192 + oA + 2048);
            ldsm4(bh[0], wbase + oB);
            ldsm4(bh[1], wbase + oB + 2048);
#pragma unroll
            for (int mi = 0; mi < 2; ++mi)
#pragma unroll
                for (int nj = 0; nj < 2; ++nj) {
                    mma16816(acc[mi][2 * nj],     ah[mi], bh[nj][0], bh[nj][1]);
                    mma16816(acc[mi][2 * nj + 1], ah[mi], bh[nj][2], bh[nj][3]);
                }
#pragma unroll
            for (int mi = 0; mi < 2; ++mi)
#pragma unroll
                for (int nj = 0; nj < 2; ++nj) {
                    mma16816(acc[mi][2 * nj],     al[mi], bh[nj][0], bh[nj][1]);
                    mma16816(acc[mi][2 * nj + 1], al[mi], bh[nj][2], bh[nj][3]);
                }
        }
    };

    float acc[2][4][4];
#pragma unroll
    for (int mi = 0; mi < 2; ++mi)
#pragma unroll
        for (int ni = 0; ni < 4; ++ni)
#pragma unroll
            for (int r = 0; r < 4; ++r) acc[mi][ni][r] = 0.f;

    // ---------------- GEMM1: pipelined over S1 subchunks --------------------
    issueX(0, XB(0));
    issueW(0, WB(0));
    CP_COMMIT();
#pragma unroll
    for (int s = 0; s < S1; ++s) {
        if (s + 1 < S1) {
            issueX(s + 1, XB((s + 1) & 1));
            issueW(s + 1, WB((s + 1) & 1));
            CP_COMMIT();
            asm volatile("cp.async.wait_group 1;" ::: "memory");
        } else {
            asm volatile("cp.async.wait_group 0;" ::: "memory");
        }
        __syncthreads();
        compute_sub(acc, sb + XB(s & 1), sb + WB(s & 1));
        __syncthreads();
    }

    // ---------------- epilogue 1: prefetch W2; h=relu(y1+b1) -> H tiles -----
    issueW(S1, WB(0));
    issueW(S1 + 1, WB(1));
    CP_COMMIT();
    {
        const float* s_b1 = (const float*)(smem + BIAS1_OFF);
#pragma unroll
        for (int mi = 0; mi < 2; ++mi) {
            const int r0 = wrow * 32 + mi * 16 + g, r1 = r0 + 8;
#pragma unroll
            for (int ni = 0; ni < 4; ++ni) {
                const int col = wcol * 32 + ni * 8 + t4 * 2;
                const float ba = s_b1[col], bb = s_b1[col + 1];
                float v0 = fmaxf(acc[mi][ni][0] + ba, 0.f);
                float v1 = fmaxf(acc[mi][ni][1] + bb, 0.f);
                float v2 = fmaxf(acc[mi][ni][2] + ba, 0.f);
                float v3 = fmaxf(acc[mi][ni][3] + bb, 0.f);
                uint32_t lo0, lo1;
                uint32_t h0 = split2h(v0, v1, lo0);
                uint32_t h1 = split2h(v2, v3, lo1);
                const int sub = col >> 6, kk = col & 63;
                const int bblk = kk >> 3, w2 = (kk & 7) * 2;
                char* tb = smem + sub * 16384;
                char* d0 = tb + r0 * 128 + (((bblk ^ (r0 & 7))) << 4) + w2;
                char* d1 = tb + r1 * 128 + (((bblk ^ (r1 & 7))) << 4) + w2;
                *(uint32_t*)d0 = h0;
                *(uint32_t*)(d0 + 8192) = lo0;
                *(uint32_t*)d1 = h1;
                *(uint32_t*)(d1 + 8192) = lo1;
            }
        }
        // reset accumulators for GEMM2 (register reuse)
#pragma unroll
        for (int mi = 0; mi < 2; ++mi)
#pragma unroll
            for (int ni = 0; ni < 4; ++ni)
#pragma unroll
                for (int r = 0; r < 4; ++r) acc[mi][ni][r] = 0.f;
    }
    asm volatile("cp.async.wait_group 0;" ::: "memory");
    __syncthreads();

    // ---------------- GEMM2: 2 subchunks (H in XB0/XB1, W2 in WB0/WB1) ------
    compute_sub(acc, sb + XB(0), sb + WB(0));
    compute_sub(acc, sb + XB(1), sb + WB(1));

    // ---------------- epilogue 2: LayerNorm + residual + scatter ------------
    {
        const float* s_b2 = (const float*)(smem + BIAS2_OFF);
        float s[2][2] = {{0.f, 0.f}, {0.f, 0.f}};
        float ss[2][2] = {{0.f, 0.f}, {0.f, 0.f}};
#pragma unroll
        for (int mi = 0; mi < 2; ++mi)
#pragma unroll
            for (int ni = 0; ni < 4; ++ni) {
                const int col = wcol * 32 + ni * 8 + t4 * 2;
                const float ba = s_b2[col], bb = s_b2[col + 1];
                float y0 = acc[mi][ni][0] + ba, y1 = acc[mi][ni][1] + bb;
                float y2 = acc[mi][ni][2] + ba, y3 = acc[mi][ni][3] + bb;
                acc[mi][ni][0] = y0; acc[mi][ni][1] = y1;
                acc[mi][ni][2] = y2; acc[mi][ni][3] = y3;
                s[mi][0] += y0 + y1; ss[mi][0] += y0 * y0 + y1 * y1;
                s[mi][1] += y2 + y3; ss[mi][1] += y2 * y2 + y3 * y3;
            }
#pragma unroll
        for (int off = 1; off <= 2; off <<= 1)
#pragma unroll
            for (int mi = 0; mi < 2; ++mi)
#pragma unroll
                for (int h = 0; h < 2; ++h) {
                    s[mi][h] += __shfl_xor_sync(0xffffffffu, s[mi][h], off);
                    ss[mi][h] += __shfl_xor_sync(0xffffffffu, ss[mi][h], off);
                }
        float2* part = (float2*)(smem + PART_OFF);
        if (t4 == 0)
#pragma unroll
            for (int mi = 0; mi < 2; ++mi)
#pragma unroll
                for (int h = 0; h < 2; ++h) {
                    const int row = wrow * 32 + mi * 16 + g + h * 8;
                    part[row * 4 + wcol] = make_float2(s[mi][h], ss[mi][h]);
                }
        __syncthreads();

        const float* s_g = (const float*)(smem + GAM_OFF);
        const float* s_bb = (const float*)(smem + BET_OFF);
#pragma unroll
        for (int mi = 0; mi < 2; ++mi)
#pragma unroll
            for (int h = 0; h < 2; ++h) {
                const int row = wrow * 32 + mi * 16 + g + h * 8;
                if (row >= valid) continue;
                float2 p0 = part[row * 4], p1 = part[row * 4 + 1];
                float2 p2 = part[row * 4 + 2], p3 = part[row * 4 + 3];
                const float mu = (p0.x + p1.x + p2.x + p3.x) * (1.f / 128.f);
                const float var =
                    (p0.y + p1.y + p2.y + p3.y) * (1.f / 128.f) - mu * mu;
                const float inv = rsqrtf(var + LN_EPS);
                const size_t gro = (size_t)(base + row) * 128;
                const float* res = (EDGE ? ef : nf) + gro;
                float* op = out + gro;
                float* ap = nullptr;
                if (EDGE) {
                    const int rv = ((const int*)(smem + RIDX_OFF))[row];
                    ap = g_agg + (size_t)rv * 128;
                }
#pragma unroll
                for (int ni = 0; ni < 4; ++ni) {
                    const int col = wcol * 32 + ni * 8 + t4 * 2;
                    const float y0 = acc[mi][ni][h * 2];
                    const float y1 = acc[mi][ni][h * 2 + 1];
                    const float m0 = (y0 - mu) * inv * s_g[col] + s_bb[col];
                    const float m1 = (y1 - mu) * inv * s_g[col + 1] + s_bb[col + 1];
                    if (EDGE) red_add_v2(ap + col, m0, m1);
                    float2 r2 = *(const float2*)(res + col);
                    *(float2*)(op + col) = make_float2(m0 + r2.x, m1 + r2.y);
                }
            }
    }
}

// ---------------------------------------------------------------------------
extern "C" void kernel_launch(void* const* d_in, const int* in_sizes, int n_in,
                              void* d_out, int out_size) {
    const float* nf  = (const float*)d_in[0];
    const float* ef  = (const float*)d_in[1];
    const int*   snd = (const int*)d_in[2];
    const int*   rcv = (const int*)d_in[3];
    const float* We1 = (const float*)d_in[4];
    const float* be1 = (const float*)d_in[5];
    const float* We2 = (const float*)d_in[6];
    const float* be2 = (const float*)d_in[7];
    const float* ge  = (const float*)d_in[8];
    const float* bbe = (const float*)d_in[9];
    const float* Wn1 = (const float*)d_in[10];
    const float* bn1 = (const float*)d_in[11];
    const float* Wn2 = (const float*)d_in[12];
    const float* bn2 = (const float*)d_in[13];
    const float* gn  = (const float*)d_in[14];
    const float* bbn = (const float*)d_in[15];

    float* out_nodes = (float*)d_out;
    float* out_edges = out_nodes + (size_t)N_NODES * 128;

    cudaFuncSetAttribute(gnb_kernel<6, true>,
                         cudaFuncAttributeMaxDynamicSharedMemorySize, SMEM_TOTAL);
    cudaFuncSetAttribute(gnb_kernel<4, false>,
                         cudaFuncAttributeMaxDynamicSharedMemorySize, SMEM_TOTAL);

    prep_w<<<448, 256>>>(We1, We2, Wn1, Wn2);
    split_nf_kernel<<<6250, 256>>>(nf);      // 50000*32 float4s
    split_ef_kernel<<<75000, 256>>>(ef);     // 600000*32 float4s
    zero_agg_kernel<<<6250, 256>>>();

    gnb_kernel<6, true><<<N_EDGES / 64, 256, SMEM_TOTAL>>>(
        nf, ef, snd, rcv, be1, be2, ge, bbe, out_edges);

    split_agg_kernel<<<6250, 256>>>();

    gnb_kernel<4, false><<<(N_NODES + 63) / 64, 256, SMEM_TOTAL>>>(
        nf, nullptr, nullptr, nullptr, bn1, bn2, gn, bbn, out_nodes);
}

// round 9
// speedup vs baseline: 4.5245x; 1.3183x over previous
#include <cuda_runtime.h>
#include <cuda_fp16.h>
#include <cstdint>

#define N_NODES 50000
#define N_EDGES 600000
#define LN_EPS 1e-5f

// ---------------- device-global scratch (no allocations allowed) ------------
__device__ float g_agg[N_NODES * 128];
__device__ __half g_nf[N_NODES * 128];
__device__ __half g_ef[(size_t)N_EDGES * 128];
__device__ __half g_ag[N_NODES * 128];
// Weights per K-64 subchunk: [sc][8192 halves], B[n][k64] layout, fp16.
// Edge: sc 0-5 = We1 (K=384), 6-7 = We2. Node: sc 0-3 = Wn1, 4-5 = Wn2.
__device__ __half g_We[8 * 8192];
__device__ __half g_Wn[6 * 8192];

// ---------------- smem layout (bytes) ---------------------------------------
// X sub-tile buf: 64 rows x 128B (fp16). Two bufs.
// W sub-tile buf: 128 rows x 128B (fp16). Two bufs.
#define XB(i)     ((uint32_t)(i) * 8192u)
#define WB(i)     (16384u + (uint32_t)(i) * 16384u)
#define BIAS1_OFF 49152
#define BIAS2_OFF 49664
#define GAM_OFF   50176
#define BET_OFF   50688
#define SIDX_OFF  51200
#define RIDX_OFF  51456
#define PART_OFF  51712
#define SMEM_TOTAL 53760

// ---------------- helpers ----------------------------------------------------
__device__ __forceinline__ uint32_t smem_u32(const void* p) {
    uint32_t a;
    asm("{ .reg .u64 t; cvta.to.shared.u64 t, %1; cvt.u32.u64 %0, t; }"
        : "=r"(a) : "l"(p));
    return a;
}
__device__ __forceinline__ void ldsm4(uint32_t (&r)[4], uint32_t a) {
    asm volatile("ldmatrix.sync.aligned.m8n8.x4.shared.b16 {%0,%1,%2,%3}, [%4];"
                 : "=r"(r[0]), "=r"(r[1]), "=r"(r[2]), "=r"(r[3]) : "r"(a));
}
__device__ __forceinline__ void mma16816(float (&d)[4], const uint32_t (&a)[4],
                                         uint32_t b0, uint32_t b1) {
    asm volatile(
        "mma.sync.aligned.m16n8k16.row.col.f32.f16.f16.f32 "
        "{%0,%1,%2,%3}, {%4,%5,%6,%7}, {%8,%9}, {%0,%1,%2,%3};"
        : "+f"(d[0]), "+f"(d[1]), "+f"(d[2]), "+f"(d[3])
        : "r"(a[0]), "r"(a[1]), "r"(a[2]), "r"(a[3]), "r"(b0), "r"(b1));
}
__device__ __forceinline__ void red_add_v2(float* p, float a, float b) {
    asm volatile("red.global.add.v2.f32 [%0], {%1, %2};"
                 :: "l"(p), "f"(a), "f"(b) : "memory");
}
__device__ __forceinline__ void cp_async16(uint32_t d, const void* s) {
    asm volatile("cp.async.cg.shared.global [%0], [%1], 16;"
                 :: "r"(d), "l"(s) : "memory");
}
__device__ __forceinline__ void cp_async16z(uint32_t d, const void* s, uint32_t sz) {
    asm volatile("cp.async.cg.shared.global [%0], [%1], 16, %2;"
                 :: "r"(d), "l"(s), "r"(sz) : "memory");
}
#define CP_COMMIT() asm volatile("cp.async.commit_group;" ::: "memory")

// pack two fp32 -> fp16x2
__device__ __forceinline__ uint32_t pack2h(float a, float b) {
    __half2 h = __floats2half2_rn(a, b);
    return *(uint32_t*)&h;
}

// ---------------- utility kernels (device symbols referenced in DEVICE code) -
__global__ void zero_agg_kernel() {
    int i = blockIdx.x * blockDim.x + threadIdx.x;
    ((float4*)g_agg)[i] = make_float4(0.f, 0.f, 0.f, 0.f);
}
__global__ void conv_nf_kernel(const float* __restrict__ src) {
    int i = blockIdx.x * blockDim.x + threadIdx.x;   // N_NODES*32 float4s
    float4 v = ((const float4*)src)[i];
    ((uint2*)g_nf)[i] = make_uint2(pack2h(v.x, v.y), pack2h(v.z, v.w));
}
__global__ void conv_ef_kernel(const float* __restrict__ src) {
    int i = blockIdx.x * blockDim.x + threadIdx.x;   // N_EDGES*32 float4s
    float4 v = ((const float4*)src)[i];
    ((uint2*)g_ef)[i] = make_uint2(pack2h(v.x, v.y), pack2h(v.z, v.w));
}
__global__ void conv_agg_kernel() {
    int i = blockIdx.x * blockDim.x + threadIdx.x;
    float4 v = ((const float4*)g_agg)[i];
    ((uint2*)g_ag)[i] = make_uint2(pack2h(v.x, v.y), pack2h(v.z, v.w));
}
__global__ void prep_w(const float* __restrict__ We1, const float* __restrict__ We2,
                       const float* __restrict__ Wn1, const float* __restrict__ Wn2) {
    int idx = blockIdx.x * blockDim.x + threadIdx.x;
    if (idx >= 114688) return;
    __half* dst;
    float v;
    int n, kk;
    if (idx < 65536) {
        int sc = idx >> 13, rem = idx & 8191;
        n = rem >> 6; kk = rem & 63;
        v = (sc < 6) ? We1[(sc * 64 + kk) * 128 + n] : We2[((sc - 6) * 64 + kk) * 128 + n];
        dst = g_We + sc * 8192;
    } else {
        int j = idx - 65536;
        int sc = j >> 13, rem = j & 8191;
        n = rem >> 6; kk = rem & 63;
        v = (sc < 4) ? Wn1[(sc * 64 + kk) * 128 + n] : Wn2[((sc - 4) * 64 + kk) * 128 + n];
        dst = g_Wn + sc * 8192;
    }
    dst[n * 64 + kk] = __float2half_rn(v);
}

// ---------------- main fused tile kernel -------------------------------------
// 256 threads, 3 CTAs/SM, 2x4 warp grid (warp tile 32x32), M tile 64.
// 1-pass fp16 GEMM, pipelined cp.async from pre-converted globals.
template <int S1, bool EDGE>
__global__ void __launch_bounds__(256, 3)
gnb_kernel(const float* __restrict__ nf, const float* __restrict__ ef,
           const int* __restrict__ snd, const int* __restrict__ rcv,
           const float* __restrict__ b1, const float* __restrict__ b2,
           const float* __restrict__ gam, const float* __restrict__ bet,
           float* __restrict__ out) {
    extern __shared__ char smem[];
    const uint32_t sb = smem_u32(smem);
    const int tid = threadIdx.x, lane = tid & 31, wid = tid >> 5;
    const int wrow = wid >> 2, wcol = wid & 3;
    const int base = blockIdx.x * 64;
    const int total = EDGE ? N_EDGES : N_NODES;
    const int valid = min(64, total - base);

    if (tid < 128) {
        ((float*)(smem + BIAS1_OFF))[tid] = b1[tid];
        ((float*)(smem + BIAS2_OFF))[tid] = b2[tid];
        ((float*)(smem + GAM_OFF))[tid] = gam[tid];
        ((float*)(smem + BET_OFF))[tid] = bet[tid];
    }
    if (EDGE && tid < 64) {
        ((int*)(smem + SIDX_OFF))[tid] = (tid < valid) ? snd[base + tid] : 0;
        ((int*)(smem + RIDX_OFF))[tid] = (tid < valid) ? rcv[base + tid] : 0;
    }
    __syncthreads();

    // per-lane ldsm constants (swizzled: block b at row r lives at (b ^ (r&7))*16)
    const int aHi = lane >> 4;
    const int rA = wrow * 32 + (lane & 15);
    const int xA = rA & 7;
    const uint32_t aRow = (uint32_t)rA * 128;
    const int bHi = (lane >> 3) & 1;
    const int rB = wcol * 32 + (lane & 7) + ((lane >> 4) << 3);
    const int xB = rB & 7;
    const uint32_t bRow = (uint32_t)rB * 128;
    const int g = lane >> 2, t4 = lane & 3;

    auto issueW = [&](int sc, uint32_t woff) {
        const __half* gW = EDGE ? g_We : g_Wn;
#pragma unroll
        for (int p = 0; p < 4; ++p) {
            int m = p * 256 + tid;                  // 1024 16B chunks
            int row = m >> 3, b = m & 7;
            const __half* src = gW + sc * 8192 + row * 64 + b * 8;
            uint32_t dst = sb + woff + (uint32_t)row * 128 +
                           (uint32_t)((b ^ (row & 7)) << 4);
            cp_async16(dst, src);
        }
    };
    auto issueX = [&](int s, uint32_t xoff) {
        const int cs = s >> 1, kh = s & 1;
#pragma unroll
        for (int p = 0; p < 2; ++p) {
            int m = p * 256 + tid;                  // 512 16B chunks
            int row = m >> 3, b = m & 7;
            int gr;
            const __half* sH;
            if (EDGE) {
                if (cs == 0) {
                    gr = ((const int*)(smem + SIDX_OFF))[row];
                    sH = g_nf;
                } else if (cs == 1) {
                    gr = ((const int*)(smem + RIDX_OFF))[row];
                    sH = g_nf;
                } else {
                    gr = base + row;
                    sH = g_ef;
                }
            } else {
                gr = base + row;
                if (gr >= total) gr = total - 1;
                sH = (cs == 0) ? g_nf : g_ag;
            }
            const __half* src = sH + (size_t)gr * 128 + kh * 64 + b * 8;
            uint32_t dst = sb + xoff + (uint32_t)row * 128 +
                           (uint32_t)((b ^ (row & 7)) << 4);
            cp_async16z(dst, src, (row < valid) ? 16u : 0u);
        }
    };
    // 64-wide-K subchunk: acc += X*W, 1-pass fp16.
    auto compute_sub = [&](float (&acc)[2][4][4], uint32_t xbase, uint32_t wbase) {
#pragma unroll
        for (int ks = 0; ks < 4; ++ks) {
            const uint32_t oA = aRow + (uint32_t)((((2 * ks + aHi) ^ xA)) << 4);
            const uint32_t oB = bRow + (uint32_t)((((2 * ks + bHi) ^ xB)) << 4);
            uint32_t ah[2][4], bh[2][4];
            ldsm4(ah[0], xbase + oA);
            ldsm4(ah[1], xbase + oA + 2048);
            ldsm4(bh[0], wbase + oB);
            ldsm4(bh[1], wbase + oB + 2048);
#pragma unroll
            for (int mi = 0; mi < 2; ++mi)
#pragma unroll
                for (int nj = 0; nj < 2; ++nj) {
                    mma16816(acc[mi][2 * nj],     ah[mi], bh[nj][0], bh[nj][1]);
                    mma16816(acc[mi][2 * nj + 1], ah[mi], bh[nj][2], bh[nj][3]);
                }
        }
    };

    float acc[2][4][4];
#pragma unroll
    for (int mi = 0; mi < 2; ++mi)
#pragma unroll
        for (int ni = 0; ni < 4; ++ni)
#pragma unroll
            for (int r = 0; r < 4; ++r) acc[mi][ni][r] = 0.f;

    // ---------------- GEMM1: pipelined over S1 subchunks --------------------
    issueX(0, XB(0));
    issueW(0, WB(0));
    CP_COMMIT();
#pragma unroll
    for (int s = 0; s < S1; ++s) {
        if (s + 1 < S1) {
            issueX(s + 1, XB((s + 1) & 1));
            issueW(s + 1, WB((s + 1) & 1));
            CP_COMMIT();
            asm volatile("cp.async.wait_group 1;" ::: "memory");
        } else {
            asm volatile("cp.async.wait_group 0;" ::: "memory");
        }
        __syncthreads();
        compute_sub(acc, sb + XB(s & 1), sb + WB(s & 1));
        __syncthreads();
    }

    // ---------------- epilogue 1: prefetch W2; h=relu(y1+b1) -> H tiles -----
    issueW(S1, WB(0));
    issueW(S1 + 1, WB(1));
    CP_COMMIT();
    {
        const float* s_b1 = (const float*)(smem + BIAS1_OFF);
#pragma unroll
        for (int mi = 0; mi < 2; ++mi) {
            const int r0 = wrow * 32 + mi * 16 + g, r1 = r0 + 8;
#pragma unroll
            for (int ni = 0; ni < 4; ++ni) {
                const int col = wcol * 32 + ni * 8 + t4 * 2;
                const float ba = s_b1[col], bb = s_b1[col + 1];
                float v0 = fmaxf(acc[mi][ni][0] + ba, 0.f);
                float v1 = fmaxf(acc[mi][ni][1] + bb, 0.f);
                float v2 = fmaxf(acc[mi][ni][2] + ba, 0.f);
                float v3 = fmaxf(acc[mi][ni][3] + bb, 0.f);
                uint32_t h0 = pack2h(v0, v1);
                uint32_t h1 = pack2h(v2, v3);
                const int sub = col >> 6, kk = col & 63;
                const int bblk = kk >> 3, w2 = (kk & 7) * 2;
                char* tb = smem + sub * 8192;     // H subchunk -> XB(sub)
                char* d0 = tb + r0 * 128 + (((bblk ^ (r0 & 7))) << 4) + w2;
                char* d1 = tb + r1 * 128 + (((bblk ^ (r1 & 7))) << 4) + w2;
                *(uint32_t*)d0 = h0;
                *(uint32_t*)d1 = h1;
            }
        }
        // reset accumulators for GEMM2 (register reuse)
#pragma unroll
        for (int mi = 0; mi < 2; ++mi)
#pragma unroll
            for (int ni = 0; ni < 4; ++ni)
#pragma unroll
                for (int r = 0; r < 4; ++r) acc[mi][ni][r] = 0.f;
    }
    asm volatile("cp.async.wait_group 0;" ::: "memory");
    __syncthreads();

    // ---------------- GEMM2: 2 subchunks (H in XB0/XB1, W2 in WB0/WB1) ------
    compute_sub(acc, sb + XB(0), sb + WB(0));
    compute_sub(acc, sb + XB(1), sb + WB(1));

    // ---------------- epilogue 2: LayerNorm + residual + scatter ------------
    {
        const float* s_b2 = (const float*)(smem + BIAS2_OFF);
        float s[2][2] = {{0.f, 0.f}, {0.f, 0.f}};
        float ss[2][2] = {{0.f, 0.f}, {0.f, 0.f}};
#pragma unroll
        for (int mi = 0; mi < 2; ++mi)
#pragma unroll
            for (int ni = 0; ni < 4; ++ni) {
                const int col = wcol * 32 + ni * 8 + t4 * 2;
                const float ba = s_b2[col], bb = s_b2[col + 1];
                float y0 = acc[mi][ni][0] + ba, y1 = acc[mi][ni][1] + bb;
                float y2 = acc[mi][ni][2] + ba, y3 = acc[mi][ni][3] + bb;
                acc[mi][ni][0] = y0; acc[mi][ni][1] = y1;
                acc[mi][ni][2] = y2; acc[mi][ni][3] = y3;
                s[mi][0] += y0 + y1; ss[mi][0] += y0 * y0 + y1 * y1;
                s[mi][1] += y2 + y3; ss[mi][1] += y2 * y2 + y3 * y3;
            }
#pragma unroll
        for (int off = 1; off <= 2; off <<= 1)
#pragma unroll
            for (int mi = 0; mi < 2; ++mi)
#pragma unroll
                for (int h = 0; h < 2; ++h) {
                    s[mi][h] += __shfl_xor_sync(0xffffffffu, s[mi][h], off);
                    ss[mi][h] += __shfl_xor_sync(0xffffffffu, ss[mi][h], off);
                }
        float2* part = (float2*)(smem + PART_OFF);
        if (t4 == 0)
#pragma unroll
            for (int mi = 0; mi < 2; ++mi)
#pragma unroll
                for (int h = 0; h < 2; ++h) {
                    const int row = wrow * 32 + mi * 16 + g + h * 8;
                    part[row * 4 + wcol] = make_float2(s[mi][h], ss[mi][h]);
                }
        __syncthreads();

        const float* s_g = (const float*)(smem + GAM_OFF);
        const float* s_bb = (const float*)(smem + BET_OFF);
#pragma unroll
        for (int mi = 0; mi < 2; ++mi)
#pragma unroll
            for (int h = 0; h < 2; ++h) {
                const int row = wrow * 32 + mi * 16 + g + h * 8;
                if (row >= valid) continue;
                float2 p0 = part[row * 4], p1 = part[row * 4 + 1];
                float2 p2 = part[row * 4 + 2], p3 = part[row * 4 + 3];
                const float mu = (p0.x + p1.x + p2.x + p3.x) * (1.f / 128.f);
                const float var =
                    (p0.y + p1.y + p2.y + p3.y) * (1.f / 128.f) - mu * mu;
                const float inv = rsqrtf(var + LN_EPS);
                const size_t gro = (size_t)(base + row) * 128;
                const float* res = (EDGE ? ef : nf) + gro;
                float* op = out + gro;
                float* ap = nullptr;
                if (EDGE) {
                    const int rv = ((const int*)(smem + RIDX_OFF))[row];
                    ap = g_agg + (size_t)rv * 128;
                }
#pragma unroll
                for (int ni = 0; ni < 4; ++ni) {
                    const int col = wcol * 32 + ni * 8 + t4 * 2;
                    const float y0 = acc[mi][ni][h * 2];
                    const float y1 = acc[mi][ni][h * 2 + 1];
                    const float m0 = (y0 - mu) * inv * s_g[col] + s_bb[col];
                    const float m1 = (y1 - mu) * inv * s_g[col + 1] + s_bb[col + 1];
                    if (EDGE) red_add_v2(ap + col, m0, m1);
                    float2 r2 = *(const float2*)(res + col);
                    *(float2*)(op + col) = make_float2(m0 + r2.x, m1 + r2.y);
                }
            }
    }
}

// ---------------------------------------------------------------------------
extern "C" void kernel_launch(void* const* d_in, const int* in_sizes, int n_in,
                              void* d_out, int out_size) {
    const float* nf  = (const float*)d_in[0];
    const float* ef  = (const float*)d_in[1];
    const int*   snd = (const int*)d_in[2];
    const int*   rcv = (const int*)d_in[3];
    const float* We1 = (const float*)d_in[4];
    const float* be1 = (const float*)d_in[5];
    const float* We2 = (const float*)d_in[6];
    const float* be2 = (const float*)d_in[7];
    const float* ge  = (const float*)d_in[8];
    const float* bbe = (const float*)d_in[9];
    const float* Wn1 = (const float*)d_in[10];
    const float* bn1 = (const float*)d_in[11];
    const float* Wn2 = (const float*)d_in[12];
    const float* bn2 = (const float*)d_in[13];
    const float* gn  = (const float*)d_in[14];
    const float* bbn = (const float*)d_in[15];

    float* out_nodes = (float*)d_out;
    float* out_edges = out_nodes + (size_t)N_NODES * 128;

    cudaFuncSetAttribute(gnb_kernel<6, true>,
                         cudaFuncAttributeMaxDynamicSharedMemorySize, SMEM_TOTAL);
    cudaFuncSetAttribute(gnb_kernel<4, false>,
                         cudaFuncAttributeMaxDynamicSharedMemorySize, SMEM_TOTAL);

    prep_w<<<448, 256>>>(We1, We2, Wn1, Wn2);
    conv_nf_kernel<<<6250, 256>>>(nf);       // 50000*32 float4s
    conv_ef_kernel<<<75000, 256>>>(ef);      // 600000*32 float4s
    zero_agg_kernel<<<6250, 256>>>();

    gnb_kernel<6, true><<<N_EDGES / 64, 256, SMEM_TOTAL>>>(
        nf, ef, snd, rcv, be1, be2, ge, bbe, out_edges);

    conv_agg_kernel<<<6250, 256>>>();

    gnb_kernel<4, false><<<(N_NODES + 63) / 64, 256, SMEM_TOTAL>>>(
        nf, nullptr, nullptr, nullptr, bn1, bn2, gn, bbn, out_nodes);
}

// round 11
// speedup vs baseline: 4.8730x; 1.0770x over previous
#include <cuda_runtime.h>
#include <cuda_fp16.h>
#include <cstdint>

#define N_NODES 50000
#define N_EDGES 600000
#define LN_EPS 1e-5f

// ---------------- device-global scratch (no allocations allowed) ------------
__device__ float g_agg[N_NODES * 128];
__device__ __half g_nf[N_NODES * 128];
__device__ __half g_ag[N_NODES * 128];
// Weights per K-64 subchunk: [sc][8192 halves], B[n][k64] layout, fp16.
// Edge: sc 0-5 = We1 (K=384), 6-7 = We2. Node: sc 0-3 = Wn1, 4-5 = Wn2.
__device__ __half g_We[8 * 8192];
__device__ __half g_Wn[6 * 8192];

// ---------------- smem layout (bytes) ---------------------------------------
// X sub-tile buf: 64 rows x 128B (fp16). Two bufs.
// W sub-tile buf: 128 rows x 128B (fp16). Two bufs.
#define XB(i)     ((uint32_t)(i) * 8192u)
#define WB(i)     (16384u + (uint32_t)(i) * 16384u)
#define BIAS1_OFF 49152
#define BIAS2_OFF 49664
#define GAM_OFF   50176
#define BET_OFF   50688
#define SIDX_OFF  51200
#define RIDX_OFF  51456
#define PART_OFF  51712
#define SMEM_TOTAL 53760

// ---------------- helpers ----------------------------------------------------
__device__ __forceinline__ uint32_t smem_u32(const void* p) {
    uint32_t a;
    asm("{ .reg .u64 t; cvta.to.shared.u64 t, %1; cvt.u32.u64 %0, t; }"
        : "=r"(a) : "l"(p));
    return a;
}
__device__ __forceinline__ void ldsm4(uint32_t (&r)[4], uint32_t a) {
    asm volatile("ldmatrix.sync.aligned.m8n8.x4.shared.b16 {%0,%1,%2,%3}, [%4];"
                 : "=r"(r[0]), "=r"(r[1]), "=r"(r[2]), "=r"(r[3]) : "r"(a));
}
__device__ __forceinline__ void mma16816(float (&d)[4], const uint32_t (&a)[4],
                                         uint32_t b0, uint32_t b1) {
    asm volatile(
        "mma.sync.aligned.m16n8k16.row.col.f32.f16.f16.f32 "
        "{%0,%1,%2,%3}, {%4,%5,%6,%7}, {%8,%9}, {%0,%1,%2,%3};"
        : "+f"(d[0]), "+f"(d[1]), "+f"(d[2]), "+f"(d[3])
        : "r"(a[0]), "r"(a[1]), "r"(a[2]), "r"(a[3]), "r"(b0), "r"(b1));
}
__device__ __forceinline__ void red_add_v2(float* p, float a, float b) {
    asm volatile("red.global.add.v2.f32 [%0], {%1, %2};"
                 :: "l"(p), "f"(a), "f"(b) : "memory");
}
__device__ __forceinline__ void cp_async16(uint32_t d, const void* s) {
    asm volatile("cp.async.cg.shared.global [%0], [%1], 16;"
                 :: "r"(d), "l"(s) : "memory");
}
__device__ __forceinline__ void cp_async16z(uint32_t d, const void* s, uint32_t sz) {
    asm volatile("cp.async.cg.shared.global [%0], [%1], 16, %2;"
                 :: "r"(d), "l"(s), "r"(sz) : "memory");
}
#define CP_COMMIT() asm volatile("cp.async.commit_group;" ::: "memory")
#define CP_WAIT0()  asm volatile("cp.async.wait_group 0;" ::: "memory")

// pack two fp32 -> fp16x2
__device__ __forceinline__ uint32_t pack2h(float a, float b) {
    __half2 h = __floats2half2_rn(a, b);
    return *(uint32_t*)&h;
}

// ---------------- utility kernels (device symbols referenced in DEVICE code) -
__global__ void zero_agg_kernel() {
    int i = blockIdx.x * blockDim.x + threadIdx.x;
    ((float4*)g_agg)[i] = make_float4(0.f, 0.f, 0.f, 0.f);
}
__global__ void conv_nf_kernel(const float* __restrict__ src) {
    int i = blockIdx.x * blockDim.x + threadIdx.x;   // N_NODES*32 float4s
    float4 v = ((const float4*)src)[i];
    ((uint2*)g_nf)[i] = make_uint2(pack2h(v.x, v.y), pack2h(v.z, v.w));
}
__global__ void conv_agg_kernel() {
    int i = blockIdx.x * blockDim.x + threadIdx.x;
    float4 v = ((const float4*)g_agg)[i];
    ((uint2*)g_ag)[i] = make_uint2(pack2h(v.x, v.y), pack2h(v.z, v.w));
}
__global__ void prep_w(const float* __restrict__ We1, const float* __restrict__ We2,
                       const float* __restrict__ Wn1, const float* __restrict__ Wn2) {
    int idx = blockIdx.x * blockDim.x + threadIdx.x;
    if (idx >= 114688) return;
    __half* dst;
    float v;
    int n, kk;
    if (idx < 65536) {
        int sc = idx >> 13, rem = idx & 8191;
        n = rem >> 6; kk = rem & 63;
        v = (sc < 6) ? We1[(sc * 64 + kk) * 128 + n] : We2[((sc - 6) * 64 + kk) * 128 + n];
        dst = g_We + sc * 8192;
    } else {
        int j = idx - 65536;
        int sc = j >> 13, rem = j & 8191;
        n = rem >> 6; kk = rem & 63;
        v = (sc < 4) ? Wn1[(sc * 64 + kk) * 128 + n] : Wn2[((sc - 4) * 64 + kk) * 128 + n];
        dst = g_Wn + sc * 8192;
    }
    dst[n * 64 + kk] = __float2half_rn(v);
}

// ---------------- main fused tile kernel -------------------------------------
// 256 threads, 3 CTAs/SM, 2x4 warp grid (warp tile 32x32), M tile 64.
// 1-pass fp16 GEMM, pipelined cp.async; EDGE converts ef fp32 inline via
// LDG-prefetch (one subchunk ahead) + cvt-on-arrival + STS.
template <int S1, bool EDGE>
__global__ void __launch_bounds__(256, 3)
gnb_kernel(const float* __restrict__ nf, const float* __restrict__ ef,
           const int* __restrict__ snd, const int* __restrict__ rcv,
           const float* __restrict__ b1, const float* __restrict__ b2,
           const float* __restrict__ gam, const float* __restrict__ bet,
           float* __restrict__ out) {
    extern __shared__ char smem[];
    const uint32_t sb = smem_u32(smem);
    const int tid = threadIdx.x, lane = tid & 31, wid = tid >> 5;
    const int wrow = wid >> 2, wcol = wid & 3;
    const int base = blockIdx.x * 64;
    const int total = EDGE ? N_EDGES : N_NODES;
    const int valid = min(64, total - base);

    if (tid < 128) {
        ((float*)(smem + BIAS1_OFF))[tid] = b1[tid];
        ((float*)(smem + BIAS2_OFF))[tid] = b2[tid];
        ((float*)(smem + GAM_OFF))[tid] = gam[tid];
        ((float*)(smem + BET_OFF))[tid] = bet[tid];
    }
    if (EDGE && tid < 64) {
        ((int*)(smem + SIDX_OFF))[tid] = (tid < valid) ? snd[base + tid] : 0;
        ((int*)(smem + RIDX_OFF))[tid] = (tid < valid) ? rcv[base + tid] : 0;
    }
    __syncthreads();

    // per-lane ldsm constants (swizzled: block b at row r lives at (b ^ (r&7))*16)
    const int aHi = lane >> 4;
    const int rA = wrow * 32 + (lane & 15);
    const int xA = rA & 7;
    const uint32_t aRow = (uint32_t)rA * 128;
    const int bHi = (lane >> 3) & 1;
    const int rB = wcol * 32 + (lane & 7) + ((lane >> 4) << 3);
    const int xB = rB & 7;
    const uint32_t bRow = (uint32_t)rB * 128;
    const int g = lane >> 2, t4 = lane & 3;

    auto issueW = [&](int sc, uint32_t woff) {
        const __half* gW = EDGE ? g_We : g_Wn;
#pragma unroll
        for (int p = 0; p < 4; ++p) {
            int m = p * 256 + tid;                  // 1024 16B chunks
            int row = m >> 3, b = m & 7;
            const __half* src = gW + sc * 8192 + row * 64 + b * 8;
            uint32_t dst = sb + woff + (uint32_t)row * 128 +
                           (uint32_t)((b ^ (row & 7)) << 4);
            cp_async16(dst, src);
        }
    };
    auto issueX = [&](int s, uint32_t xoff) {
        const int cs = s >> 1, kh = s & 1;
#pragma unroll
        for (int p = 0; p < 2; ++p) {
            int m = p * 256 + tid;                  // 512 16B chunks
            int row = m >> 3, b = m & 7;
            int gr;
            const __half* sH;
            if (EDGE) {
                gr = ((const int*)(smem + (cs == 0 ? SIDX_OFF : RIDX_OFF)))[row];
                sH = g_nf;
            } else {
                gr = base + row;
                if (gr >= total) gr = total - 1;
                sH = (cs == 0) ? g_nf : g_ag;
            }
            const __half* src = sH + (size_t)gr * 128 + kh * 64 + b * 8;
            uint32_t dst = sb + xoff + (uint32_t)row * 128 +
                           (uint32_t)((b ^ (row & 7)) << 4);
            cp_async16z(dst, src, (row < valid) ? 16u : 0u);
        }
    };
    // ef fp32 prefetch (coalesced stream, one subchunk ahead), cvt on arrival
    uint32_t efreg[8];
    const int efrow = tid >> 2, efq = tid & 3;
    auto ldgEF = [&](int s) {
        const int kh = s & 1;
        const float* src = ef + (size_t)(base + efrow) * 128 + kh * 64 + efq * 16;
#pragma unroll
        for (int j = 0; j < 4; ++j) {
            float4 v = ((const float4*)src)[j];
            efreg[j * 2]     = pack2h(v.x, v.y);
            efreg[j * 2 + 1] = pack2h(v.z, v.w);
        }
    };
    auto stsEF = [&](uint32_t xoff) {
        char* tb = smem + xoff;
#pragma unroll
        for (int j = 0; j < 4; ++j) {
            const int kk = efq * 16 + j * 4;
            const int blk = kk >> 3;
            const uint32_t o = (uint32_t)efrow * 128 +
                               (uint32_t)((blk ^ (efrow & 7)) << 4) + (kk & 7) * 2;
            *(uint32_t*)(tb + o) = efreg[j * 2];
            *(uint32_t*)(tb + o + 4) = efreg[j * 2 + 1];
        }
    };
    // 64-wide-K subchunk: acc += X*W, 1-pass fp16.
    auto compute_sub = [&](float (&acc)[2][4][4], uint32_t xbase, uint32_t wbase) {
#pragma unroll
        for (int ks = 0; ks < 4; ++ks) {
            const uint32_t oA = aRow + (uint32_t)((((2 * ks + aHi) ^ xA)) << 4);
            const uint32_t oB = bRow + (uint32_t)((((2 * ks + bHi) ^ xB)) << 4);
            uint32_t ah[2][4], bh[2][4];
            ldsm4(ah[0], xbase + oA);
            ldsm4(ah[1], xbase + oA + 2048);
            ldsm4(bh[0], wbase + oB);
            ldsm4(bh[1], wbase + oB + 2048);
#pragma unroll
            for (int mi = 0; mi < 2; ++mi)
#pragma unroll
                for (int nj = 0; nj < 2; ++nj) {
                    mma16816(acc[mi][2 * nj],     ah[mi], bh[nj][0], bh[nj][1]);
                    mma16816(acc[mi][2 * nj + 1], ah[mi], bh[nj][2], bh[nj][3]);
                }
        }
    };

    float acc[2][4][4];
#pragma unroll
    for (int mi = 0; mi < 2; ++mi)
#pragma unroll
        for (int ni = 0; ni < 4; ++ni)
#pragma unroll
            for (int r = 0; r < 4; ++r) acc[mi][ni][r] = 0.f;

    // ---------------- GEMM1: pipelined over S1 subchunks --------------------
    issueX(0, XB(0));
    issueW(0, WB(0));
    CP_COMMIT();
#pragma unroll
    for (int s = 0; s < S1; ++s) {
        CP_WAIT0();
        __syncthreads();
        const bool curEF = EDGE && (s >> 1) == 2;
        if (curEF) {
            stsEF(XB(s & 1));
            __syncthreads();
        }
        if (s + 1 < S1) {
            const bool nxtEF = EDGE && ((s + 1) >> 1) == 2;
            if (nxtEF) ldgEF(s + 1);
            else       issueX(s + 1, XB((s + 1) & 1));
            issueW(s + 1, WB((s + 1) & 1));
            CP_COMMIT();
        }
        compute_sub(acc, sb + XB(s & 1), sb + WB(s & 1));
        __syncthreads();
    }

    // ---------------- W2 prefetch (safe: all GEMM1 compute done) ------------
    issueW(S1, WB(0));
    issueW(S1 + 1, WB(1));
    CP_COMMIT();

    // ---------------- epilogue 1: h = relu(y1+b1) -> H tiles ----------------
    {
        const float* s_b1 = (const float*)(smem + BIAS1_OFF);
#pragma unroll
        for (int mi = 0; mi < 2; ++mi) {
            const int r0 = wrow * 32 + mi * 16 + g, r1 = r0 + 8;
#pragma unroll
            for (int ni = 0; ni < 4; ++ni) {
                const int col = wcol * 32 + ni * 8 + t4 * 2;
                const float ba = s_b1[col], bb = s_b1[col + 1];
                float v0 = fmaxf(acc[mi][ni][0] + ba, 0.f);
                float v1 = fmaxf(acc[mi][ni][1] + bb, 0.f);
                float v2 = fmaxf(acc[mi][ni][2] + ba, 0.f);
                float v3 = fmaxf(acc[mi][ni][3] + bb, 0.f);
                uint32_t h0 = pack2h(v0, v1);
                uint32_t h1 = pack2h(v2, v3);
                const int sub = col >> 6, kk = col & 63;
                const int bblk = kk >> 3, w2 = (kk & 7) * 2;
                char* tb = smem + sub * 8192;     // H subchunk -> XB(sub)
                char* d0 = tb + r0 * 128 + (((bblk ^ (r0 & 7))) << 4) + w2;
                char* d1 = tb + r1 * 128 + (((bblk ^ (r1 & 7))) << 4) + w2;
                *(uint32_t*)d0 = h0;
                *(uint32_t*)d1 = h1;
            }
        }
        // reset accumulators for GEMM2 (register reuse)
#pragma unroll
        for (int mi = 0; mi < 2; ++mi)
#pragma unroll
            for (int ni = 0; ni < 4; ++ni)
#pragma unroll
                for (int r = 0; r < 4; ++r) acc[mi][ni][r] = 0.f;
    }
    CP_WAIT0();
    __syncthreads();

    // ---------------- GEMM2: 2 subchunks (H in XB0/XB1, W2 in WB0/WB1) ------
    compute_sub(acc, sb + XB(0), sb + WB(0));
    compute_sub(acc, sb + XB(1), sb + WB(1));

    // ---------------- epilogue 2: LayerNorm + residual + scatter ------------
    {
        const float* s_b2 = (const float*)(smem + BIAS2_OFF);
        float s[2][2] = {{0.f, 0.f}, {0.f, 0.f}};
        float ss[2][2] = {{0.f, 0.f}, {0.f, 0.f}};
#pragma unroll
        for (int mi = 0; mi < 2; ++mi)
#pragma unroll
            for (int ni = 0; ni < 4; ++ni) {
                const int col = wcol * 32 + ni * 8 + t4 * 2;
                const float ba = s_b2[col], bb = s_b2[col + 1];
                float y0 = acc[mi][ni][0] + ba, y1 = acc[mi][ni][1] + bb;
                float y2 = acc[mi][ni][2] + ba, y3 = acc[mi][ni][3] + bb;
                acc[mi][ni][0] = y0; acc[mi][ni][1] = y1;
                acc[mi][ni][2] = y2; acc[mi][ni][3] = y3;
                s[mi][0] += y0 + y1; ss[mi][0] += y0 * y0 + y1 * y1;
                s[mi][1] += y2 + y3; ss[mi][1] += y2 * y2 + y3 * y3;
            }
#pragma unroll
        for (int off = 1; off <= 2; off <<= 1)
#pragma unroll
            for (int mi = 0; mi < 2; ++mi)
#pragma unroll
                for (int h = 0; h < 2; ++h) {
                    s[mi][h] += __shfl_xor_sync(0xffffffffu, s[mi][h], off);
                    ss[mi][h] += __shfl_xor_sync(0xffffffffu, ss[mi][h], off);
                }
        float2* part = (float2*)(smem + PART_OFF);
        if (t4 == 0)
#pragma unroll
            for (int mi = 0; mi < 2; ++mi)
#pragma unroll
                for (int h = 0; h < 2; ++h) {
                    const int row = wrow * 32 + mi * 16 + g + h * 8;
                    part[row * 4 + wcol] = make_float2(s[mi][h], ss[mi][h]);
                }
        __syncthreads();

        const float* s_g = (const float*)(smem + GAM_OFF);
        const float* s_bb = (const float*)(smem + BET_OFF);
#pragma unroll
        for (int mi = 0; mi < 2; ++mi)
#pragma unroll
            for (int h = 0; h < 2; ++h) {
                const int row = wrow * 32 + mi * 16 + g + h * 8;
                if (row >= valid) continue;
                float2 p0 = part[row * 4], p1 = part[row * 4 + 1];
                float2 p2 = part[row * 4 + 2], p3 = part[row * 4 + 3];
                const float mu = (p0.x + p1.x + p2.x + p3.x) * (1.f / 128.f);
                const float var =
                    (p0.y + p1.y + p2.y + p3.y) * (1.f / 128.f) - mu * mu;
                const float inv = rsqrtf(var + LN_EPS);
                const size_t gro = (size_t)(base + row) * 128;
                const float* res = (EDGE ? ef : nf) + gro;
                float* op = out + gro;
                float* ap = nullptr;
                if (EDGE) {
                    const int rv = ((const int*)(smem + RIDX_OFF))[row];
                    ap = g_agg + (size_t)rv * 128;
                }
#pragma unroll
                for (int ni = 0; ni < 4; ++ni) {
                    const int col = wcol * 32 + ni * 8 + t4 * 2;
                    const float y0 = acc[mi][ni][h * 2];
                    const float y1 = acc[mi][ni][h * 2 + 1];
                    const float m0 = (y0 - mu) * inv * s_g[col] + s_bb[col];
                    const float m1 = (y1 - mu) * inv * s_g[col + 1] + s_bb[col + 1];
                    if (EDGE) red_add_v2(ap + col, m0, m1);
                    float2 r2 = *(const float2*)(res + col);
                    *(float2*)(op + col) = make_float2(m0 + r2.x, m1 + r2.y);
                }
            }
    }
}

// ---------------------------------------------------------------------------
extern "C" void kernel_launch(void* const* d_in, const int* in_sizes, int n_in,
                              void* d_out, int out_size) {
    const float* nf  = (const float*)d_in[0];
    const float* ef  = (const float*)d_in[1];
    const int*   snd = (const int*)d_in[2];
    const int*   rcv = (const int*)d_in[3];
    const float* We1 = (const float*)d_in[4];
    const float* be1 = (const float*)d_in[5];
    const float* We2 = (const float*)d_in[6];
    const float* be2 = (const float*)d_in[7];
    const float* ge  = (const float*)d_in[8];
    const float* bbe = (const float*)d_in[9];
    const float* Wn1 = (const float*)d_in[10];
    const float* bn1 = (const float*)d_in[11];
    const float* Wn2 = (const float*)d_in[12];
    const float* bn2 = (const float*)d_in[13];
    const float* gn  = (const float*)d_in[14];
    const float* bbn = (const float*)d_in[15];

    float* out_nodes = (float*)d_out;
    float* out_edges = out_nodes + (size_t)N_NODES * 128;

    cudaFuncSetAttribute(gnb_kernel<6, true>,
                         cudaFuncAttributeMaxDynamicSharedMemorySize, SMEM_TOTAL);
    cudaFuncSetAttribute(gnb_kernel<4, false>,
                         cudaFuncAttributeMaxDynamicSharedMemorySize, SMEM_TOTAL);

    prep_w<<<448, 256>>>(We1, We2, Wn1, Wn2);
    conv_nf_kernel<<<6250, 256>>>(nf);       // 50000*32 float4s
    zero_agg_kernel<<<6250, 256>>>();

    gnb_kernel<6, true><<<N_EDGES / 64, 256, SMEM_TOTAL>>>(
        nf, ef, snd, rcv, be1, be2, ge, bbe, out_edges);

    conv_agg_kernel<<<6250, 256>>>();

    gnb_kernel<4, false><<<(N_NODES + 63) / 64, 256, SMEM_TOTAL>>>(
        nf, nullptr, nullptr, nullptr, bn1, bn2, gn, bbn, out_nodes);
}